// round 3
// baseline (speedup 1.0000x reference)
#include <cuda_runtime.h>
#include <math.h>

// Problem constants
#define BDIM   64          // batch
#define NNODES 1024        // nodes
#define UDIM   64          // hidden units
#define FDIM   66          // D_IN + U
#define MDIM   5           // num diffusion matrices
#define NCOLS  4224        // FDIM * BDIM
#define KDIM   1024        // contraction dim of S @ X
#define XSZ    (NNODES * NCOLS)

// Scratch (device globals; no allocation allowed)
__device__ __align__(256) float g_X[5][XSZ];                 // xs[m], layout [n, f*64 + b]
__device__ __align__(256) float g_rh[BDIM * NNODES * UDIM];  // r * hx, layout like hx: [b, n*64+u]
__device__ __align__(256) float g_u [BDIM * NNODES * UDIM];  // update gate u

// ---- packed f32x2 helpers (Blackwell FFMA2: 2 FMAs per issue) ----
__device__ __forceinline__ unsigned long long dup2(float a) {
    unsigned long long r;
    asm("mov.b64 %0, {%1, %1};" : "=l"(r) : "f"(a));
    return r;
}
__device__ __forceinline__ void fma2(unsigned long long& c,
                                     unsigned long long a,
                                     unsigned long long b) {
    asm("fma.rn.f32x2 %0, %1, %2, %0;" : "+l"(c) : "l"(a), "l"(b));
}

// ============================================================================
// Kernel 1: build X0 [n, f*64+b]: f<2 from inputs, f>=2 from hsrc (hx or r*hx)
// cstart=128 on the second pass (input columns f<2 are unchanged).
// ============================================================================
__global__ void build_x0_kernel(const float* __restrict__ inp,
                                const float* __restrict__ hsrc, int cstart) {
    const int n = blockIdx.y;
    const int c = cstart + blockIdx.x * 128 + threadIdx.x;
    const int f = c >> 6;
    const int b = c & 63;
    float v = (f < 2) ? inp[b * 2048 + n * 2 + f]
                      : hsrc[(size_t)b * 65536 + n * 64 + (f - 2)];
    g_X[0][(size_t)n * NCOLS + c] = v;
}

// ============================================================================
// Kernel 2: SGEMM  C = S @ B   (CHEB: C = 2*(S @ B) - X0)
// M=1024, N=4224, K=1024. BM=BN=128, BK=16, 256 threads, 8x8/thread via f32x2.
// blockIdx.z selects support 0/1 (batched).
// ============================================================================
template <bool CHEB>
__global__ __launch_bounds__(256, 2)
void gemm_kernel(const float* __restrict__ A0c, const float* __restrict__ A1c,
                 const float* __restrict__ B0c, const float* __restrict__ B1c,
                 float* __restrict__ C0c, float* __restrict__ C1c) {
    const float* A  = blockIdx.z ? A1c : A0c;
    const float* Bm = blockIdx.z ? B1c : B0c;
    float*       C  = blockIdx.z ? C1c : C0c;

    __shared__ float As[16][132];   // transposed A tile, padded vs bank conflicts
    __shared__ float Bs[16][128];

    const int tid = threadIdx.x;
    const int tx = tid & 15;        // output cols: tx*8 .. +7
    const int ty = tid >> 4;        // output rows: ty*8 .. +7
    const int brow = blockIdx.y * 128;
    const int bcol = blockIdx.x * 128;

    const int a_row = tid >> 2;            // 0..63  (and +64)
    const int a_k   = (tid & 3) << 2;      // 0,4,8,12
    const int b_row = tid >> 5;            // 0..7   (and +8)
    const int b_col = (tid & 31) << 2;     // 0..124

    const float* Ap = A + (size_t)(brow + a_row) * KDIM + a_k;
    const float* Bp = Bm + (size_t)b_row * NCOLS + bcol + b_col;

    unsigned long long c2[8][4];
#pragma unroll
    for (int i = 0; i < 8; i++)
#pragma unroll
        for (int j = 0; j < 4; j++) c2[i][j] = 0ULL;

    for (int k0 = 0; k0 < KDIM; k0 += 16) {
        float4 av0 = *(const float4*)(Ap + k0);
        float4 av1 = *(const float4*)(Ap + (size_t)64 * KDIM + k0);
        float4 bv0 = *(const float4*)(Bp + (size_t)k0 * NCOLS);
        float4 bv1 = *(const float4*)(Bp + (size_t)(k0 + 8) * NCOLS);

        As[a_k + 0][a_row] = av0.x; As[a_k + 1][a_row] = av0.y;
        As[a_k + 2][a_row] = av0.z; As[a_k + 3][a_row] = av0.w;
        As[a_k + 0][a_row + 64] = av1.x; As[a_k + 1][a_row + 64] = av1.y;
        As[a_k + 2][a_row + 64] = av1.z; As[a_k + 3][a_row + 64] = av1.w;
        *(float4*)&Bs[b_row][b_col]     = bv0;
        *(float4*)&Bs[b_row + 8][b_col] = bv1;
        __syncthreads();

#pragma unroll
        for (int k = 0; k < 16; k++) {
            unsigned long long b2[4];
            ulonglong2 t0 = *(const ulonglong2*)&Bs[k][tx * 8];
            ulonglong2 t1 = *(const ulonglong2*)&Bs[k][tx * 8 + 4];
            b2[0] = t0.x; b2[1] = t0.y; b2[2] = t1.x; b2[3] = t1.y;
#pragma unroll
            for (int i = 0; i < 8; i++) {
                unsigned long long a2 = dup2(As[k][ty * 8 + i]);
#pragma unroll
                for (int j = 0; j < 4; j++) fma2(c2[i][j], a2, b2[j]);
            }
        }
        __syncthreads();
    }

#pragma unroll
    for (int i = 0; i < 8; i++) {
        const size_t row = brow + ty * 8 + i;
        const size_t off = row * NCOLS + bcol + tx * 8;
        float2 p0 = *(float2*)&c2[i][0];
        float2 p1 = *(float2*)&c2[i][1];
        float2 p2 = *(float2*)&c2[i][2];
        float2 p3 = *(float2*)&c2[i][3];
        float4 o0 = make_float4(p0.x, p0.y, p1.x, p1.y);
        float4 o1 = make_float4(p2.x, p2.y, p3.x, p3.y);
        if (CHEB) {
            float4 d0 = *(const float4*)&g_X[0][off];
            float4 d1 = *(const float4*)&g_X[0][off + 4];
            o0.x = 2.f * o0.x - d0.x; o0.y = 2.f * o0.y - d0.y;
            o0.z = 2.f * o0.z - d0.z; o0.w = 2.f * o0.w - d0.w;
            o1.x = 2.f * o1.x - d1.x; o1.y = 2.f * o1.y - d1.y;
            o1.z = 2.f * o1.z - d1.z; o1.w = 2.f * o1.w - d1.w;
        }
        *(float4*)&C[off]     = o0;
        *(float4*)&C[off + 4] = o1;
    }
}

// ============================================================================
// Kernel 3: projection 1 (gconv output gate). One block per node n.
// y[b, o] = sigmoid( sum_{k=0..329} A[b,k] * Wo[k,o] + bo[o] ),  o in [0,128)
//   A[b, k=f*5+m] = g_X[m][n, f*64+b]
// writes: g_rh[b,n,u] = y[:, :64] * hx,  g_u[b,n,u] = y[:, 64:]
// ============================================================================
__global__ __launch_bounds__(256, 2)
void proj1_kernel(const float* __restrict__ W, const float* __restrict__ bias,
                  const float* __restrict__ hx) {
    const int n = blockIdx.x;
    __shared__ float Asm[16][64];
    __shared__ float Wsm[16][128];
    const int tid = threadIdx.x;
    const int tx = tid & 15;          // cols o = tx*8..+7
    const int ty = tid >> 4;          // rows b = ty*4..+3
    const int lk = tid >> 4;          // load: k lane 0..15
    const int lb = (tid & 15) << 2;   // load: A b offset
    const int lo = (tid & 15) << 3;   // load: W o offset

    unsigned long long acc[4][4];
#pragma unroll
    for (int i = 0; i < 4; i++)
#pragma unroll
        for (int j = 0; j < 4; j++) acc[i][j] = 0ULL;

    for (int k0 = 0; k0 < 330; k0 += 16) {
        const int k = k0 + lk;
        float4 av  = make_float4(0.f, 0.f, 0.f, 0.f);
        float4 wv0 = av, wv1 = av;
        if (k < 330) {
            const int f = k / 5;
            const int m = k - f * 5;
            av  = *(const float4*)&g_X[m][(size_t)n * NCOLS + f * 64 + lb];
            wv0 = *(const float4*)&W[k * 128 + lo];
            wv1 = *(const float4*)&W[k * 128 + lo + 4];
        }
        __syncthreads();
        *(float4*)&Asm[lk][lb]     = av;
        *(float4*)&Wsm[lk][lo]     = wv0;
        *(float4*)&Wsm[lk][lo + 4] = wv1;
        __syncthreads();
#pragma unroll
        for (int kk = 0; kk < 16; kk++) {
            unsigned long long w2[4];
            ulonglong2 t0 = *(const ulonglong2*)&Wsm[kk][tx * 8];
            ulonglong2 t1 = *(const ulonglong2*)&Wsm[kk][tx * 8 + 4];
            w2[0] = t0.x; w2[1] = t0.y; w2[2] = t1.x; w2[3] = t1.y;
#pragma unroll
            for (int i = 0; i < 4; i++) {
                unsigned long long a2 = dup2(Asm[kk][ty * 4 + i]);
#pragma unroll
                for (int j = 0; j < 4; j++) fma2(acc[i][j], a2, w2[j]);
            }
        }
    }

#pragma unroll
    for (int i = 0; i < 4; i++) {
        const int b = ty * 4 + i;
        const size_t base = (size_t)b * 65536 + n * 64;
#pragma unroll
        for (int j = 0; j < 4; j++) {
            float2 p = *(float2*)&acc[i][j];
            const int o = tx * 8 + j * 2;
            const float s0 = 1.f / (1.f + expf(-(p.x + bias[o])));
            const float s1 = 1.f / (1.f + expf(-(p.y + bias[o + 1])));
            if (o < 64) {
                g_rh[base + o]     = s0 * hx[base + o];
                g_rh[base + o + 1] = s1 * hx[base + o + 1];
            } else {
                g_u[base + o - 64]     = s0;
                g_u[base + o - 63]     = s1;
            }
        }
    }
}

// ============================================================================
// Kernel 4: projection 2 (candidate) + final GRU combine. One block per node.
// c = tanh(A @ Wu + bu);  out = u*hx + (1-u)*c
// ============================================================================
__global__ __launch_bounds__(256, 2)
void proj2_kernel(const float* __restrict__ W, const float* __restrict__ bias,
                  const float* __restrict__ hx, float* __restrict__ out) {
    const int n = blockIdx.x;
    __shared__ float Asm[16][64];
    __shared__ float Wsm[16][64];
    const int tid = threadIdx.x;
    const int tx = tid & 7;           // cols o = tx*8..+7
    const int ty = tid >> 3;          // rows b = ty*2..+1
    const int lk = tid >> 4;          // load: k lane 0..15
    const int lb = (tid & 15) << 2;

    unsigned long long acc[2][4];
#pragma unroll
    for (int i = 0; i < 2; i++)
#pragma unroll
        for (int j = 0; j < 4; j++) acc[i][j] = 0ULL;

    for (int k0 = 0; k0 < 330; k0 += 16) {
        const int k = k0 + lk;
        float4 av = make_float4(0.f, 0.f, 0.f, 0.f);
        float4 wv = av;
        if (k < 330) {
            const int f = k / 5;
            const int m = k - f * 5;
            av = *(const float4*)&g_X[m][(size_t)n * NCOLS + f * 64 + lb];
            wv = *(const float4*)&W[k * 64 + lb];
        }
        __syncthreads();
        *(float4*)&Asm[lk][lb] = av;
        *(float4*)&Wsm[lk][lb] = wv;
        __syncthreads();
#pragma unroll
        for (int kk = 0; kk < 16; kk++) {
            unsigned long long w2[4];
            ulonglong2 t0 = *(const ulonglong2*)&Wsm[kk][tx * 8];
            ulonglong2 t1 = *(const ulonglong2*)&Wsm[kk][tx * 8 + 4];
            w2[0] = t0.x; w2[1] = t0.y; w2[2] = t1.x; w2[3] = t1.y;
#pragma unroll
            for (int i = 0; i < 2; i++) {
                unsigned long long a2 = dup2(Asm[kk][ty * 2 + i]);
#pragma unroll
                for (int j = 0; j < 4; j++) fma2(acc[i][j], a2, w2[j]);
            }
        }
    }

#pragma unroll
    for (int i = 0; i < 2; i++) {
        const int b = ty * 2 + i;
        const size_t base = (size_t)b * 65536 + n * 64;
#pragma unroll
        for (int j = 0; j < 4; j++) {
            float2 p = *(float2*)&acc[i][j];
            const int o = tx * 8 + j * 2;
            const float c0 = tanhf(p.x + bias[o]);
            const float c1 = tanhf(p.y + bias[o + 1]);
            const float u0 = g_u[base + o],     h0 = hx[base + o];
            const float u1 = g_u[base + o + 1], h1 = hx[base + o + 1];
            out[base + o]     = u0 * h0 + (1.f - u0) * c0;
            out[base + o + 1] = u1 * h1 + (1.f - u1) * c1;
        }
    }
}

// ============================================================================
// Host driver: 2 passes (gconv1 -> gates, gconv2 -> candidate + combine)
// ============================================================================
extern "C" void kernel_launch(void* const* d_in, const int* in_sizes, int n_in,
                              void* d_out, int out_size) {
    const float* inp = (const float*)d_in[0];  // [64, 2048]
    const float* hx  = (const float*)d_in[1];  // [64, 65536]
    const float* S0  = (const float*)d_in[2];  // [1024, 1024]
    const float* S1  = (const float*)d_in[3];  // [1024, 1024]
    const float* Wo  = (const float*)d_in[4];  // [330, 128]
    const float* bo  = (const float*)d_in[5];  // [128]
    const float* Wu  = (const float*)d_in[6];  // [330, 64]
    const float* bu  = (const float*)d_in[7];  // [64]
    float* out = (float*)d_out;

    float* gX  = nullptr;
    float* grh = nullptr;
    cudaGetSymbolAddress((void**)&gX,  g_X);
    cudaGetSymbolAddress((void**)&grh, g_rh);

    const dim3 gG(33, 8, 2);   // 4224/128 x 1024/128 x 2 supports

    for (int pass = 0; pass < 2; pass++) {
        if (pass == 0)
            build_x0_kernel<<<dim3(33, NNODES), 128>>>(inp, hx, 0);
        else
            build_x0_kernel<<<dim3(32, NNODES), 128>>>(inp, grh, 128);

        // xs[1] = S0@X0, xs[3] = S1@X0
        gemm_kernel<false><<<gG, 256>>>(S0, S1, gX, gX,
                                        gX + 1 * (size_t)XSZ, gX + 3 * (size_t)XSZ);
        // xs[2] = 2*S0@xs[1] - X0, xs[4] = 2*S1@xs[3] - X0
        gemm_kernel<true><<<gG, 256>>>(S0, S1,
                                       gX + 1 * (size_t)XSZ, gX + 3 * (size_t)XSZ,
                                       gX + 2 * (size_t)XSZ, gX + 4 * (size_t)XSZ);

        if (pass == 0)
            proj1_kernel<<<NNODES, 256>>>(Wo, bo, hx);
        else
            proj2_kernel<<<NNODES, 256>>>(Wu, bu, hx, out);
    }
}

// round 7
// speedup vs baseline: 1.7342x; 1.7342x over previous
#include <cuda_runtime.h>
#include <cuda_bf16.h>
#include <cstdint>
#include <math.h>

// ---------------- Problem constants ----------------
#define BDIM   64
#define NNODES 1024
#define UDIM   64
#define NCOLS  4224          // 66 features * 64 batch
#define NM     5
#define XTSZ   (NCOLS * NNODES)

// GEMM tiling: C[i,j] = sum_k S[i,k] * X[k,j]; X,C stored transposed XT[j][i]
#define MT 128
#define NT 128
#define KC 32                // k per stage
#define NCHUNK 32            // 1024 / 32
#define ROWB 80              // smem row pitch bytes (32 bf16 = 64B + 16B pad)
#define REG_BYTES (128 * ROWB)        // 10240 per operand region
#define OFF_AH 0
#define OFF_AL (1 * REG_BYTES)
#define OFF_BH (2 * REG_BYTES)
#define OFF_BL (3 * REG_BYTES)
#define STAGE_BYTES (4 * REG_BYTES)   // 40960
#define DSMEM_BYTES (2 * STAGE_BYTES) // 81920 (>= epilogue 128*133*4=68096)

// ---------------- Device scratch ----------------
__device__ __align__(256) __nv_bfloat16 g_XTh[NM][XTSZ];
__device__ __align__(256) __nv_bfloat16 g_XTl[NM][XTSZ];
__device__ __align__(256) __nv_bfloat16 g_Sh[2][1024 * 1024];
__device__ __align__(256) __nv_bfloat16 g_Sl[2][1024 * 1024];
__device__ __align__(256) float g_rh[BDIM * NNODES * UDIM];
__device__ __align__(256) float g_u [BDIM * NNODES * UDIM];

// ---------------- helpers ----------------
__device__ __forceinline__ uint32_t smem_u32(const void* p) {
    uint32_t a;
    asm("{ .reg .u64 t; cvta.to.shared.u64 t, %1; cvt.u32.u64 %0, t; }" : "=r"(a) : "l"(p));
    return a;
}
__device__ __forceinline__ void cp16(uint32_t saddr, const void* gaddr) {
    asm volatile("cp.async.cg.shared.global [%0], [%1], 16;" :: "r"(saddr), "l"(gaddr));
}
__device__ __forceinline__ void ldmx4(uint32_t& r0, uint32_t& r1, uint32_t& r2, uint32_t& r3,
                                      uint32_t addr) {
    asm volatile("ldmatrix.sync.aligned.m8n8.x4.shared.b16 {%0,%1,%2,%3}, [%4];"
                 : "=r"(r0), "=r"(r1), "=r"(r2), "=r"(r3) : "r"(addr));
}
__device__ __forceinline__ void mma16816(float* c, const uint32_t* a, uint32_t b0, uint32_t b1) {
    asm volatile(
        "mma.sync.aligned.m16n8k16.row.col.f32.bf16.bf16.f32 "
        "{%0,%1,%2,%3}, {%4,%5,%6,%7}, {%8,%9}, {%0,%1,%2,%3};"
        : "+f"(c[0]), "+f"(c[1]), "+f"(c[2]), "+f"(c[3])
        : "r"(a[0]), "r"(a[1]), "r"(a[2]), "r"(a[3]), "r"(b0), "r"(b1));
}
// fp32x2 packed helpers (projection kernels)
__device__ __forceinline__ unsigned long long dup2(float a) {
    unsigned long long r;
    asm("mov.b64 %0, {%1, %1};" : "=l"(r) : "f"(a));
    return r;
}
__device__ __forceinline__ void fma2(unsigned long long& c, unsigned long long a,
                                     unsigned long long b) {
    asm("fma.rn.f32x2 %0, %1, %2, %0;" : "+l"(c) : "l"(a), "l"(b));
}
__device__ __forceinline__ float b2f(uint32_t bits16) {
    return __int_as_float((int)(bits16 << 16));
}

// ============================================================================
// split S into bf16 hi/lo
// ============================================================================
__global__ void split_s_kernel(const float* __restrict__ S0, const float* __restrict__ S1) {
    int idx = blockIdx.x * 256 + threadIdx.x;
    int z = idx >> 20;
    int e = idx & 1048575;
    float v = (z ? S1 : S0)[e];
    __nv_bfloat16 h = __float2bfloat16(v);
    g_Sh[z][e] = h;
    g_Sl[z][e] = __float2bfloat16(v - __bfloat162float(h));
}

// build XT0 input rows c in [0,128)
__global__ void build_inp_kernel(const float* __restrict__ inp) {
    int idx = blockIdx.x * 256 + threadIdx.x;           // 128*1024
    int c = idx >> 10, i = idx & 1023;
    int f = c >> 6, b = c & 63;
    float v = inp[b * 2048 + i * 2 + f];
    __nv_bfloat16 h = __float2bfloat16(v);
    g_XTh[0][c * 1024 + i] = h;
    g_XTl[0][c * 1024 + i] = __float2bfloat16(v - __bfloat162float(h));
}

// build XT0 hidden rows c in [128,4224)
__global__ void build_h_kernel(const float* __restrict__ hsrc) {
    int idx = blockIdx.x * 256 + threadIdx.x;           // 4096*1024
    int c = 128 + (idx >> 10);
    int i = idx & 1023;
    int u = (c >> 6) - 2, b = c & 63;
    float v = hsrc[(size_t)b * 65536 + i * 64 + u];
    __nv_bfloat16 h = __float2bfloat16(v);
    g_XTh[0][(size_t)c * 1024 + i] = h;
    g_XTl[0][(size_t)c * 1024 + i] = __float2bfloat16(v - __bfloat162float(h));
}

// ============================================================================
// bf16x3 mma.sync GEMM: C = S[z] @ X[mi]  (CHEB: C = 2C - X0) -> XT[mo]
// grid (33, 8, 2), 256 threads.
// ============================================================================
template <bool CHEB>
__global__ __launch_bounds__(256)
void gemm_mma(int inBase, int inStride, int outBase) {
    const int z = blockIdx.z;
    const int it = blockIdx.y, jt = blockIdx.x;
    const int mi_idx = inBase + z * inStride;
    const int mo = outBase + 2 * z;

    const __nv_bfloat16* __restrict__ Ah = g_Sh[z];
    const __nv_bfloat16* __restrict__ Al = g_Sl[z];
    const __nv_bfloat16* __restrict__ Bh = g_XTh[mi_idx];
    const __nv_bfloat16* __restrict__ Bl = g_XTl[mi_idx];
    __nv_bfloat16* __restrict__ Ch = g_XTh[mo];
    __nv_bfloat16* __restrict__ Cl = g_XTl[mo];

    extern __shared__ char sm[];
    const uint32_t sb0 = smem_u32(sm);

    const int tid = threadIdx.x;
    const int warp = tid >> 5;
    const int lane = tid & 31;
    const int wm = warp >> 2;          // 0..1 : rows wm*64
    const int wn = warp & 3;           // 0..3 : cols wn*32

    // global load base offsets (bf16 elements)
    const size_t arow0 = (size_t)(it * MT) * 1024;
    const size_t brow0 = (size_t)(jt * NT) * 1024;

    // per-thread ldmatrix address components
    const uint32_t a_lm = (uint32_t)((lane & 15) * ROWB + ((lane >> 4) << 4));
    const uint32_t b_lm = (uint32_t)((((lane >> 4) << 3) + (lane & 7)) * ROWB +
                                     (((lane >> 3) & 1) << 4));

    float acc[4][4][4];
#pragma unroll
    for (int i = 0; i < 4; i++)
#pragma unroll
        for (int j = 0; j < 4; j++)
#pragma unroll
            for (int r = 0; r < 4; r++) acc[i][j][r] = 0.f;

    // ---- stage loader: 2048 cp.async of 16B, 8 per thread ----
    auto issue = [&](int c) {
        const int buf = c & 1;
        const int k0 = c * KC;
        const uint32_t sbase = sb0 + buf * STAGE_BYTES;
#pragma unroll
        for (int q = 0; q < 8; q++) {
            int idx = tid + q * 256;
            int region = idx >> 9;             // 0..3
            int row = (idx >> 2) & 127;
            int seg = idx & 3;
            const __nv_bfloat16* gp;
            if (region == 0)      gp = Ah + arow0;
            else if (region == 1) gp = Al + arow0;
            else if (region == 2) gp = Bh + brow0;
            else                  gp = Bl + brow0;
            gp += (size_t)row * 1024 + k0 + seg * 8;
            cp16(sbase + region * REG_BYTES + row * ROWB + seg * 16, gp);
        }
        asm volatile("cp.async.commit_group;" ::: "memory");
    };

    issue(0);

    for (int c = 0; c < NCHUNK; ++c) {
        if (c + 1 < NCHUNK) {
            issue(c + 1);
            asm volatile("cp.async.wait_group 1;" ::: "memory");
        } else {
            asm volatile("cp.async.wait_group 0;" ::: "memory");
        }
        __syncthreads();

        const uint32_t sbase = sb0 + (c & 1) * STAGE_BYTES;
        const uint32_t aB = sbase + a_lm + (uint32_t)(wm * 64) * ROWB;
        const uint32_t bB = sbase + b_lm + (uint32_t)(wn * 32) * ROWB;

#pragma unroll
        for (int s = 0; s < 2; ++s) {          // two k16 steps
            const uint32_t ks = (uint32_t)(s << 5);   // step*16 elems = 32 bytes
            uint32_t bh[2][4], bl[2][4];
#pragma unroll
            for (int p = 0; p < 2; ++p) {
                ldmx4(bh[p][0], bh[p][1], bh[p][2], bh[p][3],
                      bB + OFF_BH + (uint32_t)(p * 16) * ROWB + ks);
                ldmx4(bl[p][0], bl[p][1], bl[p][2], bl[p][3],
                      bB + OFF_BL + (uint32_t)(p * 16) * ROWB + ks);
            }
#pragma unroll
            for (int mi = 0; mi < 4; ++mi) {
                uint32_t ah[4], al[4];
                ldmx4(ah[0], ah[1], ah[2], ah[3],
                      aB + OFF_AH + (uint32_t)(mi * 16) * ROWB + ks);
                ldmx4(al[0], al[1], al[2], al[3],
                      aB + OFF_AL + (uint32_t)(mi * 16) * ROWB + ks);
#pragma unroll
                for (int nj = 0; nj < 4; ++nj) {
                    const int p = nj >> 1, h = (nj & 1) << 1;
                    mma16816(acc[mi][nj], ah, bh[p][h], bh[p][h + 1]);
                    mma16816(acc[mi][nj], ah, bl[p][h], bl[p][h + 1]);
                    mma16816(acc[mi][nj], al, bh[p][h], bh[p][h + 1]);
                }
            }
        }
        __syncthreads();
    }

    // ---- epilogue: stage C tile in smem (stride 133 floats, odd -> the
    // column reads below are conflict-free; stores MUST be scalar because
    // odd*133+even is 4-mod-8 bytes: a float2 store traps) ----
    float* Csm = (float*)sm;
    const int gid = lane >> 2;        // 0..7
    const int tig = lane & 3;         // 0..3
#pragma unroll
    for (int mi = 0; mi < 4; ++mi) {
#pragma unroll
        for (int nj = 0; nj < 4; ++nj) {
            const int r0 = wm * 64 + mi * 16 + gid;
            const int n = wn * 32 + nj * 8 + 2 * tig;
            Csm[r0 * 133 + n]           = acc[mi][nj][0];
            Csm[r0 * 133 + n + 1]       = acc[mi][nj][1];
            Csm[(r0 + 8) * 133 + n]     = acc[mi][nj][2];
            Csm[(r0 + 8) * 133 + n + 1] = acc[mi][nj][3];
        }
    }
    __syncthreads();

#pragma unroll 1
    for (int iter = 0; iter < 16; ++iter) {
        const int j = iter * 8 + warp;
        const size_t jg = (size_t)(jt * NT + j);
#pragma unroll
        for (int q = 0; q < 4; ++q) {
            const int i = lane + q * 32;
            const size_t ig = (size_t)(it * MT) + i;
            float y = Csm[i * 133 + j];
            if (CHEB) {
                float x0 = __bfloat162float(g_XTh[0][jg * 1024 + ig]) +
                           __bfloat162float(g_XTl[0][jg * 1024 + ig]);
                y = 2.f * y - x0;
            }
            __nv_bfloat16 h = __float2bfloat16(y);
            Ch[jg * 1024 + ig] = h;
            Cl[jg * 1024 + ig] = __float2bfloat16(y - __bfloat162float(h));
        }
    }
}

// ============================================================================
// proj1: Y[n,o] = sigmoid(sum_k A[k][n]*W[k][o] + bias);  A[k=(f,m)][n] = XT_m[f*64+b][n]
// r -> g_rh = r*hx ; u -> g_u
// ============================================================================
__global__ __launch_bounds__(256, 2)
void proj1_kernel(const float* __restrict__ W, const float* __restrict__ bias,
                  const float* __restrict__ hx) {
    const int n0 = blockIdx.x * 64;
    const int b  = blockIdx.y;
    __shared__ float Asm[16][64];
    __shared__ float Wsm[16][128];
    const int tid = threadIdx.x;
    const int tx = tid & 15;
    const int ty = tid >> 4;
    const int lk = tid >> 4;
    const int ln = tid & 15;

    unsigned long long acc[4][4];
#pragma unroll
    for (int i = 0; i < 4; i++)
#pragma unroll
        for (int j = 0; j < 4; j++) acc[i][j] = 0ULL;

    for (int k0 = 0; k0 < 330; k0 += 16) {
        const int k = k0 + lk;
        float a0 = 0.f, a1 = 0.f, a2 = 0.f, a3 = 0.f;
        float4 wv0 = make_float4(0.f, 0.f, 0.f, 0.f), wv1 = wv0;
        if (k < 330) {
            const int f = k / 5;
            const int m = k - f * 5;
            const size_t off = (size_t)(f * 64 + b) * 1024 + n0 + ln * 4;
            uint2 hv = *(const uint2*)(&g_XTh[m][off]);
            uint2 lv = *(const uint2*)(&g_XTl[m][off]);
            a0 = b2f(hv.x & 0xFFFF) + b2f(lv.x & 0xFFFF);
            a1 = b2f(hv.x >> 16)    + b2f(lv.x >> 16);
            a2 = b2f(hv.y & 0xFFFF) + b2f(lv.y & 0xFFFF);
            a3 = b2f(hv.y >> 16)    + b2f(lv.y >> 16);
            wv0 = *(const float4*)&W[k * 128 + ln * 8];
            wv1 = *(const float4*)&W[k * 128 + ln * 8 + 4];
        }
        __syncthreads();
        Asm[lk][ln * 4 + 0] = a0; Asm[lk][ln * 4 + 1] = a1;
        Asm[lk][ln * 4 + 2] = a2; Asm[lk][ln * 4 + 3] = a3;
        *(float4*)&Wsm[lk][ln * 8]     = wv0;
        *(float4*)&Wsm[lk][ln * 8 + 4] = wv1;
        __syncthreads();
#pragma unroll
        for (int kk = 0; kk < 16; kk++) {
            unsigned long long w2[4];
            ulonglong2 t0 = *(const ulonglong2*)&Wsm[kk][tx * 8];
            ulonglong2 t1 = *(const ulonglong2*)&Wsm[kk][tx * 8 + 4];
            w2[0] = t0.x; w2[1] = t0.y; w2[2] = t1.x; w2[3] = t1.y;
#pragma unroll
            for (int i = 0; i < 4; i++) {
                unsigned long long a2r = dup2(Asm[kk][ty * 4 + i]);
#pragma unroll
                for (int j = 0; j < 4; j++) fma2(acc[i][j], a2r, w2[j]);
            }
        }
    }

#pragma unroll
    for (int i = 0; i < 4; i++) {
        const int n = n0 + ty * 4 + i;
        const size_t base = (size_t)b * 65536 + n * 64;
#pragma unroll
        for (int j = 0; j < 4; j++) {
            float2 p = *(float2*)&acc[i][j];
            const int o = tx * 8 + j * 2;
            const float s0 = 1.f / (1.f + expf(-(p.x + bias[o])));
            const float s1 = 1.f / (1.f + expf(-(p.y + bias[o + 1])));
            if (o < 64) {
                g_rh[base + o]     = s0 * hx[base + o];
                g_rh[base + o + 1] = s1 * hx[base + o + 1];
            } else {
                g_u[base + o - 64] = s0;
                g_u[base + o - 63] = s1;
            }
        }
    }
}

// ============================================================================
// proj2: c = tanh(A@Wu + bu);  out = u*hx + (1-u)*c
// ============================================================================
__global__ __launch_bounds__(256, 2)
void proj2_kernel(const float* __restrict__ W, const float* __restrict__ bias,
                  const float* __restrict__ hx, float* __restrict__ out) {
    const int n0 = blockIdx.x * 64;
    const int b  = blockIdx.y;
    __shared__ float Asm[16][64];
    __shared__ float Wsm[16][64];
    const int tid = threadIdx.x;
    const int tx = tid & 7;
    const int ty = tid >> 3;
    const int lk = tid >> 4;
    const int ln = tid & 15;

    unsigned long long acc[2][4];
#pragma unroll
    for (int i = 0; i < 2; i++)
#pragma unroll
        for (int j = 0; j < 4; j++) acc[i][j] = 0ULL;

    for (int k0 = 0; k0 < 330; k0 += 16) {
        const int k = k0 + lk;
        float a0 = 0.f, a1 = 0.f, a2 = 0.f, a3 = 0.f;
        float4 wv = make_float4(0.f, 0.f, 0.f, 0.f);
        if (k < 330) {
            const int f = k / 5;
            const int m = k - f * 5;
            const size_t off = (size_t)(f * 64 + b) * 1024 + n0 + ln * 4;
            uint2 hv = *(const uint2*)(&g_XTh[m][off]);
            uint2 lv = *(const uint2*)(&g_XTl[m][off]);
            a0 = b2f(hv.x & 0xFFFF) + b2f(lv.x & 0xFFFF);
            a1 = b2f(hv.x >> 16)    + b2f(lv.x >> 16);
            a2 = b2f(hv.y & 0xFFFF) + b2f(lv.y & 0xFFFF);
            a3 = b2f(hv.y >> 16)    + b2f(lv.y >> 16);
            wv = *(const float4*)&W[k * 64 + ln * 4];
        }
        __syncthreads();
        Asm[lk][ln * 4 + 0] = a0; Asm[lk][ln * 4 + 1] = a1;
        Asm[lk][ln * 4 + 2] = a2; Asm[lk][ln * 4 + 3] = a3;
        *(float4*)&Wsm[lk][ln * 4] = wv;
        __syncthreads();
#pragma unroll
        for (int kk = 0; kk < 16; kk++) {
            unsigned long long w2[4];
            ulonglong2 t0 = *(const ulonglong2*)&Wsm[kk][tx * 8];
            ulonglong2 t1 = *(const ulonglong2*)&Wsm[kk][tx * 8 + 4];
            w2[0] = t0.x; w2[1] = t0.y; w2[2] = t1.x; w2[3] = t1.y;
#pragma unroll
            for (int i = 0; i < 2; i++) {
                unsigned long long a2r = dup2(Asm[kk][ty * 2 + i]);
#pragma unroll
                for (int j = 0; j < 4; j++) fma2(acc[i][j], a2r, w2[j]);
            }
        }
    }

#pragma unroll
    for (int i = 0; i < 2; i++) {
        const int n = n0 + ty * 2 + i;
        const size_t base = (size_t)b * 65536 + n * 64;
#pragma unroll
        for (int j = 0; j < 4; j++) {
            float2 p = *(float2*)&acc[i][j];
            const int o = tx * 8 + j * 2;
            const float c0 = tanhf(p.x + bias[o]);
            const float c1 = tanhf(p.y + bias[o + 1]);
            const float u0 = g_u[base + o],     h0 = hx[base + o];
            const float u1 = g_u[base + o + 1], h1 = hx[base + o + 1];
            out[base + o]     = u0 * h0 + (1.f - u0) * c0;
            out[base + o + 1] = u1 * h1 + (1.f - u1) * c1;
        }
    }
}

// ============================================================================
// Host driver
// ============================================================================
extern "C" void kernel_launch(void* const* d_in, const int* in_sizes, int n_in,
                              void* d_out, int out_size) {
    const float* inp = (const float*)d_in[0];
    const float* hx  = (const float*)d_in[1];
    const float* S0  = (const float*)d_in[2];
    const float* S1  = (const float*)d_in[3];
    const float* Wo  = (const float*)d_in[4];
    const float* bo  = (const float*)d_in[5];
    const float* Wu  = (const float*)d_in[6];
    const float* bu  = (const float*)d_in[7];
    float* out = (float*)d_out;

    cudaFuncSetAttribute(gemm_mma<false>, cudaFuncAttributeMaxDynamicSharedMemorySize, DSMEM_BYTES);
    cudaFuncSetAttribute(gemm_mma<true>,  cudaFuncAttributeMaxDynamicSharedMemorySize, DSMEM_BYTES);

    float* grh = nullptr;
    cudaGetSymbolAddress((void**)&grh, g_rh);

    split_s_kernel<<<8192, 256>>>(S0, S1);
    build_inp_kernel<<<512, 256>>>(inp);

    const dim3 gG(NCOLS / NT, NNODES / MT, 2);   // (33, 8, 2)

    for (int pass = 0; pass < 2; pass++) {
        build_h_kernel<<<16384, 256>>>(pass == 0 ? hx : grh);
        // xs1 = S0@X0 -> XT1 ; xs3 = S1@X0 -> XT3
        gemm_mma<false><<<gG, 256, DSMEM_BYTES>>>(0, 0, 1);
        // xs2 = 2*S0@XT1 - X0 -> XT2 ; xs4 = 2*S1@XT3 - X0 -> XT4
        gemm_mma<true><<<gG, 256, DSMEM_BYTES>>>(1, 2, 2);

        if (pass == 0)
            proj1_kernel<<<dim3(16, 64), 256>>>(Wo, bo, hx);
        else
            proj2_kernel<<<dim3(16, 64), 256>>>(Wu, bu, hx, out);
    }
}

// round 8
// speedup vs baseline: 1.7343x; 1.0001x over previous
#include <cuda_runtime.h>
#include <cuda_bf16.h>
#include <cstdint>
#include <math.h>

// ---------------- Problem constants ----------------
#define BDIM   64
#define NNODES 1024
#define UDIM   64
#define NCOLS  4224          // 66 features * 64 batch
#define NM     5
#define XTSZ   (NCOLS * NNODES)

// GEMM tiling: C[i,j] = sum_k S[i,k] * X[k,j]; X,C stored transposed XT[j][i]
#define MT 256
#define NT 128
#define KC 32                // k per stage
#define NCHUNK 32            // 1024 / 32
#define ROWB 80              // smem row pitch bytes (32 bf16 = 64B + 16B pad)
#define OFF_AH 0
#define OFF_AL 20480                  // 256*80
#define OFF_BH 40960
#define OFF_BL 51200                  // + 128*80
#define STAGE_BYTES 61440
#define DSMEM_BYTES (2 * STAGE_BYTES) // 122880 (>= epilogue 128*133*4=68096)

// ---------------- Device scratch ----------------
__device__ __align__(256) __nv_bfloat16 g_XTh[NM][XTSZ];
__device__ __align__(256) __nv_bfloat16 g_XTl[NM][XTSZ];
__device__ __align__(256) __nv_bfloat16 g_Sh[2][1024 * 1024];
__device__ __align__(256) __nv_bfloat16 g_Sl[2][1024 * 1024];
__device__ __align__(256) float g_rh[BDIM * NNODES * UDIM];
__device__ __align__(256) float g_u [BDIM * NNODES * UDIM];

// ---------------- helpers ----------------
__device__ __forceinline__ uint32_t smem_u32(const void* p) {
    uint32_t a;
    asm("{ .reg .u64 t; cvta.to.shared.u64 t, %1; cvt.u32.u64 %0, t; }" : "=r"(a) : "l"(p));
    return a;
}
__device__ __forceinline__ void cp16(uint32_t saddr, const void* gaddr) {
    asm volatile("cp.async.cg.shared.global [%0], [%1], 16;" :: "r"(saddr), "l"(gaddr));
}
__device__ __forceinline__ void ldmx4(uint32_t& r0, uint32_t& r1, uint32_t& r2, uint32_t& r3,
                                      uint32_t addr) {
    asm volatile("ldmatrix.sync.aligned.m8n8.x4.shared.b16 {%0,%1,%2,%3}, [%4];"
                 : "=r"(r0), "=r"(r1), "=r"(r2), "=r"(r3) : "r"(addr));
}
__device__ __forceinline__ void mma16816(float* c, const uint32_t* a, uint32_t b0, uint32_t b1) {
    asm volatile(
        "mma.sync.aligned.m16n8k16.row.col.f32.bf16.bf16.f32 "
        "{%0,%1,%2,%3}, {%4,%5,%6,%7}, {%8,%9}, {%0,%1,%2,%3};"
        : "+f"(c[0]), "+f"(c[1]), "+f"(c[2]), "+f"(c[3])
        : "r"(a[0]), "r"(a[1]), "r"(a[2]), "r"(a[3]), "r"(b0), "r"(b1));
}
// fp32x2 packed helpers (projection kernels)
__device__ __forceinline__ unsigned long long dup2(float a) {
    unsigned long long r;
    asm("mov.b64 %0, {%1, %1};" : "=l"(r) : "f"(a));
    return r;
}
__device__ __forceinline__ void fma2(unsigned long long& c, unsigned long long a,
                                     unsigned long long b) {
    asm("fma.rn.f32x2 %0, %1, %2, %0;" : "+l"(c) : "l"(a), "l"(b));
}
__device__ __forceinline__ float b2f(uint32_t bits16) {
    return __int_as_float((int)(bits16 << 16));
}

// ============================================================================
// split S into bf16 hi/lo
// ============================================================================
__global__ void split_s_kernel(const float* __restrict__ S0, const float* __restrict__ S1) {
    int idx = blockIdx.x * 256 + threadIdx.x;
    int z = idx >> 20;
    int e = idx & 1048575;
    float v = (z ? S1 : S0)[e];
    __nv_bfloat16 h = __float2bfloat16(v);
    g_Sh[z][e] = h;
    g_Sl[z][e] = __float2bfloat16(v - __bfloat162float(h));
}

// build XT0 input rows c in [0,128)
__global__ void build_inp_kernel(const float* __restrict__ inp) {
    int idx = blockIdx.x * 256 + threadIdx.x;           // 128*1024
    int c = idx >> 10, i = idx & 1023;
    int f = c >> 6, b = c & 63;
    float v = inp[b * 2048 + i * 2 + f];
    __nv_bfloat16 h = __float2bfloat16(v);
    g_XTh[0][c * 1024 + i] = h;
    g_XTl[0][c * 1024 + i] = __float2bfloat16(v - __bfloat162float(h));
}

// ============================================================================
// build XT0 hidden rows via smem transpose (fully coalesced both sides).
// grid (16 i-tiles, 64 b), 256 threads. Tile: 64 u x 64 i.
// XT0[(u+2)*64 + b][i] = hsrc[b*65536 + i*64 + u]
// ============================================================================
__global__ __launch_bounds__(256)
void build_h_kernel(const float* __restrict__ hsrc) {
    __shared__ float T[64][65];
    const int i0 = blockIdx.x * 64;
    const int b  = blockIdx.y;
    const int tid = threadIdx.x;

    {   // load: consecutive threads -> consecutive u (coalesced 256B rows)
        const int u = tid & 63;
        const int iib = tid >> 6;           // 0..3
#pragma unroll
        for (int w = 0; w < 16; ++w) {
            const int ii = iib + w * 4;
            T[u][ii] = hsrc[(size_t)b * 65536 + (size_t)(i0 + ii) * 64 + u];
        }
    }
    __syncthreads();
    {   // store: consecutive threads -> consecutive i (coalesced)
        const int ii = tid & 63;
        const int ub = tid >> 6;            // 0..3
#pragma unroll
        for (int w = 0; w < 16; ++w) {
            const int u = ub + w * 4;
            float v = T[u][ii];
            __nv_bfloat16 h = __float2bfloat16(v);
            const size_t off = (size_t)((u + 2) * 64 + b) * 1024 + i0 + ii;
            g_XTh[0][off] = h;
            g_XTl[0][off] = __float2bfloat16(v - __bfloat162float(h));
        }
    }
}

// ============================================================================
// bf16x3 mma.sync GEMM: C = S[z] @ X[mi]  (CHEB: C = 2C - X0) -> XT[mo]
// grid (33, 4, 2), 512 threads (16 warps, 4x4), warp tile 64x32.
// ============================================================================
template <bool CHEB>
__global__ __launch_bounds__(512)
void gemm_mma(int inBase, int inStride, int outBase) {
    const int z = blockIdx.z;
    const int it = blockIdx.y, jt = blockIdx.x;
    const int mi_idx = inBase + z * inStride;
    const int mo = outBase + 2 * z;

    const __nv_bfloat16* __restrict__ Ah = g_Sh[z];
    const __nv_bfloat16* __restrict__ Al = g_Sl[z];
    const __nv_bfloat16* __restrict__ Bh = g_XTh[mi_idx];
    const __nv_bfloat16* __restrict__ Bl = g_XTl[mi_idx];
    __nv_bfloat16* __restrict__ Ch = g_XTh[mo];
    __nv_bfloat16* __restrict__ Cl = g_XTl[mo];

    extern __shared__ char sm[];
    const uint32_t sb0 = smem_u32(sm);

    const int tid = threadIdx.x;
    const int warp = tid >> 5;
    const int lane = tid & 31;
    const int wm = warp >> 2;          // 0..3 : rows wm*64
    const int wn = warp & 3;           // 0..3 : cols wn*32

    const size_t arow0 = (size_t)(it * MT) * 1024;
    const size_t brow0 = (size_t)(jt * NT) * 1024;

    // per-thread ldmatrix address components
    const uint32_t a_lm = (uint32_t)((lane & 15) * ROWB + ((lane >> 4) << 4));
    const uint32_t b_lm = (uint32_t)((((lane >> 4) << 3) + (lane & 7)) * ROWB +
                                     (((lane >> 3) & 1) << 4));

    float acc[4][4][4];
#pragma unroll
    for (int i = 0; i < 4; i++)
#pragma unroll
        for (int j = 0; j < 4; j++)
#pragma unroll
            for (int r = 0; r < 4; r++) acc[i][j][r] = 0.f;

    // ---- stage loader: 3072 cp.async of 16B, 6 per thread ----
    auto issue = [&](int c) {
        const int buf = c & 1;
        const int k0 = c * KC;
        const uint32_t sbase = sb0 + buf * STAGE_BYTES;
#pragma unroll
        for (int q = 0; q < 6; q++) {
            int idx = tid + q * 512;
            const __nv_bfloat16* gp;
            uint32_t moff; size_t r0; int li;
            if (idx < 1024)      { gp = Ah; moff = OFF_AH; r0 = arow0; li = idx; }
            else if (idx < 2048) { gp = Al; moff = OFF_AL; r0 = arow0; li = idx - 1024; }
            else if (idx < 2560) { gp = Bh; moff = OFF_BH; r0 = brow0; li = idx - 2048; }
            else                 { gp = Bl; moff = OFF_BL; r0 = brow0; li = idx - 2560; }
            const int row = li >> 2, seg = li & 3;
            cp16(sbase + moff + row * ROWB + seg * 16,
                 gp + r0 + (size_t)row * 1024 + k0 + seg * 8);
        }
        asm volatile("cp.async.commit_group;" ::: "memory");
    };

    issue(0);

    for (int c = 0; c < NCHUNK; ++c) {
        if (c + 1 < NCHUNK) {
            issue(c + 1);
            asm volatile("cp.async.wait_group 1;" ::: "memory");
        } else {
            asm volatile("cp.async.wait_group 0;" ::: "memory");
        }
        __syncthreads();

        const uint32_t sbase = sb0 + (c & 1) * STAGE_BYTES;
        const uint32_t aB = sbase + a_lm + (uint32_t)(wm * 64) * ROWB;
        const uint32_t bB = sbase + b_lm + (uint32_t)(wn * 32) * ROWB;

#pragma unroll
        for (int s = 0; s < 2; ++s) {          // two k16 steps
            const uint32_t ks = (uint32_t)(s << 5);   // step*16 elems = 32 bytes
            uint32_t bh[2][4], bl[2][4];
#pragma unroll
            for (int p = 0; p < 2; ++p) {
                ldmx4(bh[p][0], bh[p][1], bh[p][2], bh[p][3],
                      bB + OFF_BH + (uint32_t)(p * 16) * ROWB + ks);
                ldmx4(bl[p][0], bl[p][1], bl[p][2], bl[p][3],
                      bB + OFF_BL + (uint32_t)(p * 16) * ROWB + ks);
            }
#pragma unroll
            for (int mi = 0; mi < 4; ++mi) {
                uint32_t ah[4], al[4];
                ldmx4(ah[0], ah[1], ah[2], ah[3],
                      aB + OFF_AH + (uint32_t)(mi * 16) * ROWB + ks);
                ldmx4(al[0], al[1], al[2], al[3],
                      aB + OFF_AL + (uint32_t)(mi * 16) * ROWB + ks);
#pragma unroll
                for (int nj = 0; nj < 4; ++nj) {
                    const int p = nj >> 1, h = (nj & 1) << 1;
                    mma16816(acc[mi][nj], ah, bh[p][h], bh[p][h + 1]);
                    mma16816(acc[mi][nj], ah, bl[p][h], bl[p][h + 1]);
                    mma16816(acc[mi][nj], al, bh[p][h], bh[p][h + 1]);
                }
            }
        }
        __syncthreads();
    }

    // ---- epilogue in two 128-row halves (stride 133 floats, odd ->
    // conflict-free column reads; scalar stores: odd*133+even is 4-mod-8 B) ----
    float* Csm = (float*)sm;
    const int gid = lane >> 2;        // 0..7
    const int tig = lane & 3;         // 0..3
#pragma unroll 1
    for (int hhalf = 0; hhalf < 2; ++hhalf) {
        if ((wm >> 1) == hhalf) {
#pragma unroll
            for (int mi = 0; mi < 4; ++mi) {
#pragma unroll
                for (int nj = 0; nj < 4; ++nj) {
                    const int r0 = (wm & 1) * 64 + mi * 16 + gid;
                    const int n = wn * 32 + nj * 8 + 2 * tig;
                    Csm[r0 * 133 + n]           = acc[mi][nj][0];
                    Csm[r0 * 133 + n + 1]       = acc[mi][nj][1];
                    Csm[(r0 + 8) * 133 + n]     = acc[mi][nj][2];
                    Csm[(r0 + 8) * 133 + n + 1] = acc[mi][nj][3];
                }
            }
        }
        __syncthreads();

#pragma unroll 1
        for (int iter = 0; iter < 8; ++iter) {
            const int j = iter * 16 + warp;
            const size_t jg = (size_t)(jt * NT + j);
#pragma unroll
            for (int q = 0; q < 4; ++q) {
                const int i = lane + q * 32;
                const size_t ig = (size_t)(it * MT) + hhalf * 128 + i;
                float y = Csm[i * 133 + j];
                if (CHEB) {
                    float x0 = __bfloat162float(g_XTh[0][jg * 1024 + ig]) +
                               __bfloat162float(g_XTl[0][jg * 1024 + ig]);
                    y = 2.f * y - x0;
                }
                __nv_bfloat16 h = __float2bfloat16(y);
                Ch[jg * 1024 + ig] = h;
                Cl[jg * 1024 + ig] = __float2bfloat16(y - __bfloat162float(h));
            }
        }
        __syncthreads();
    }
}

// ============================================================================
// proj1: Y[n,o] = sigmoid(sum_k A[k][n]*W[k][o] + bias);  A[k=(f,m)][n] = XT_m[f*64+b][n]
// r -> g_rh = r*hx ; u -> g_u
// ============================================================================
__global__ __launch_bounds__(256, 2)
void proj1_kernel(const float* __restrict__ W, const float* __restrict__ bias,
                  const float* __restrict__ hx) {
    const int n0 = blockIdx.x * 64;
    const int b  = blockIdx.y;
    __shared__ float Asm[16][64];
    __shared__ float Wsm[16][128];
    const int tid = threadIdx.x;
    const int tx = tid & 15;
    const int ty = tid >> 4;
    const int lk = tid >> 4;
    const int ln = tid & 15;

    unsigned long long acc[4][4];
#pragma unroll
    for (int i = 0; i < 4; i++)
#pragma unroll
        for (int j = 0; j < 4; j++) acc[i][j] = 0ULL;

    for (int k0 = 0; k0 < 330; k0 += 16) {
        const int k = k0 + lk;
        float a0 = 0.f, a1 = 0.f, a2 = 0.f, a3 = 0.f;
        float4 wv0 = make_float4(0.f, 0.f, 0.f, 0.f), wv1 = wv0;
        if (k < 330) {
            const int f = k / 5;
            const int m = k - f * 5;
            const size_t off = (size_t)(f * 64 + b) * 1024 + n0 + ln * 4;
            uint2 hv = *(const uint2*)(&g_XTh[m][off]);
            uint2 lv = *(const uint2*)(&g_XTl[m][off]);
            a0 = b2f(hv.x & 0xFFFF) + b2f(lv.x & 0xFFFF);
            a1 = b2f(hv.x >> 16)    + b2f(lv.x >> 16);
            a2 = b2f(hv.y & 0xFFFF) + b2f(lv.y & 0xFFFF);
            a3 = b2f(hv.y >> 16)    + b2f(lv.y >> 16);
            wv0 = *(const float4*)&W[k * 128 + ln * 8];
            wv1 = *(const float4*)&W[k * 128 + ln * 8 + 4];
        }
        __syncthreads();
        Asm[lk][ln * 4 + 0] = a0; Asm[lk][ln * 4 + 1] = a1;
        Asm[lk][ln * 4 + 2] = a2; Asm[lk][ln * 4 + 3] = a3;
        *(float4*)&Wsm[lk][ln * 8]     = wv0;
        *(float4*)&Wsm[lk][ln * 8 + 4] = wv1;
        __syncthreads();
#pragma unroll
        for (int kk = 0; kk < 16; kk++) {
            unsigned long long w2[4];
            ulonglong2 t0 = *(const ulonglong2*)&Wsm[kk][tx * 8];
            ulonglong2 t1 = *(const ulonglong2*)&Wsm[kk][tx * 8 + 4];
            w2[0] = t0.x; w2[1] = t0.y; w2[2] = t1.x; w2[3] = t1.y;
#pragma unroll
            for (int i = 0; i < 4; i++) {
                unsigned long long a2r = dup2(Asm[kk][ty * 4 + i]);
#pragma unroll
                for (int j = 0; j < 4; j++) fma2(acc[i][j], a2r, w2[j]);
            }
        }
    }

#pragma unroll
    for (int i = 0; i < 4; i++) {
        const int n = n0 + ty * 4 + i;
        const size_t base = (size_t)b * 65536 + n * 64;
#pragma unroll
        for (int j = 0; j < 4; j++) {
            float2 p = *(float2*)&acc[i][j];
            const int o = tx * 8 + j * 2;
            const float s0 = 1.f / (1.f + expf(-(p.x + bias[o])));
            const float s1 = 1.f / (1.f + expf(-(p.y + bias[o + 1])));
            if (o < 64) {
                g_rh[base + o]     = s0 * hx[base + o];
                g_rh[base + o + 1] = s1 * hx[base + o + 1];
            } else {
                g_u[base + o - 64] = s0;
                g_u[base + o - 63] = s1;
            }
        }
    }
}

// ============================================================================
// proj2: c = tanh(A@Wu + bu);  out = u*hx + (1-u)*c
// ============================================================================
__global__ __launch_bounds__(256, 2)
void proj2_kernel(const float* __restrict__ W, const float* __restrict__ bias,
                  const float* __restrict__ hx, float* __restrict__ out) {
    const int n0 = blockIdx.x * 64;
    const int b  = blockIdx.y;
    __shared__ float Asm[16][64];
    __shared__ float Wsm[16][64];
    const int tid = threadIdx.x;
    const int tx = tid & 7;
    const int ty = tid >> 3;
    const int lk = tid >> 4;
    const int ln = tid & 15;

    unsigned long long acc[2][4];
#pragma unroll
    for (int i = 0; i < 2; i++)
#pragma unroll
        for (int j = 0; j < 4; j++) acc[i][j] = 0ULL;

    for (int k0 = 0; k0 < 330; k0 += 16) {
        const int k = k0 + lk;
        float a0 = 0.f, a1 = 0.f, a2 = 0.f, a3 = 0.f;
        float4 wv = make_float4(0.f, 0.f, 0.f, 0.f);
        if (k < 330) {
            const int f = k / 5;
            const int m = k - f * 5;
            const size_t off = (size_t)(f * 64 + b) * 1024 + n0 + ln * 4;
            uint2 hv = *(const uint2*)(&g_XTh[m][off]);
            uint2 lv = *(const uint2*)(&g_XTl[m][off]);
            a0 = b2f(hv.x & 0xFFFF) + b2f(lv.x & 0xFFFF);
            a1 = b2f(hv.x >> 16)    + b2f(lv.x >> 16);
            a2 = b2f(hv.y & 0xFFFF) + b2f(lv.y & 0xFFFF);
            a3 = b2f(hv.y >> 16)    + b2f(lv.y >> 16);
            wv = *(const float4*)&W[k * 64 + ln * 4];
        }
        __syncthreads();
        Asm[lk][ln * 4 + 0] = a0; Asm[lk][ln * 4 + 1] = a1;
        Asm[lk][ln * 4 + 2] = a2; Asm[lk][ln * 4 + 3] = a3;
        *(float4*)&Wsm[lk][ln * 4] = wv;
        __syncthreads();
#pragma unroll
        for (int kk = 0; kk < 16; kk++) {
            unsigned long long w2[4];
            ulonglong2 t0 = *(const ulonglong2*)&Wsm[kk][tx * 8];
            ulonglong2 t1 = *(const ulonglong2*)&Wsm[kk][tx * 8 + 4];
            w2[0] = t0.x; w2[1] = t0.y; w2[2] = t1.x; w2[3] = t1.y;
#pragma unroll
            for (int i = 0; i < 2; i++) {
                unsigned long long a2r = dup2(Asm[kk][ty * 2 + i]);
#pragma unroll
                for (int j = 0; j < 4; j++) fma2(acc[i][j], a2r, w2[j]);
            }
        }
    }

#pragma unroll
    for (int i = 0; i < 2; i++) {
        const int n = n0 + ty * 2 + i;
        const size_t base = (size_t)b * 65536 + n * 64;
#pragma unroll
        for (int j = 0; j < 4; j++) {
            float2 p = *(float2*)&acc[i][j];
            const int o = tx * 8 + j * 2;
            const float c0 = tanhf(p.x + bias[o]);
            const float c1 = tanhf(p.y + bias[o + 1]);
            const float u0 = g_u[base + o],     h0 = hx[base + o];
            const float u1 = g_u[base + o + 1], h1 = hx[base + o + 1];
            out[base + o]     = u0 * h0 + (1.f - u0) * c0;
            out[base + o + 1] = u1 * h1 + (1.f - u1) * c1;
        }
    }
}

// ============================================================================
// Host driver
// ============================================================================
extern "C" void kernel_launch(void* const* d_in, const int* in_sizes, int n_in,
                              void* d_out, int out_size) {
    const float* inp = (const float*)d_in[0];
    const float* hx  = (const float*)d_in[1];
    const float* S0  = (const float*)d_in[2];
    const float* S1  = (const float*)d_in[3];
    const float* Wo  = (const float*)d_in[4];
    const float* bo  = (const float*)d_in[5];
    const float* Wu  = (const float*)d_in[6];
    const float* bu  = (const float*)d_in[7];
    float* out = (float*)d_out;

    cudaFuncSetAttribute(gemm_mma<false>, cudaFuncAttributeMaxDynamicSharedMemorySize, DSMEM_BYTES);
    cudaFuncSetAttribute(gemm_mma<true>,  cudaFuncAttributeMaxDynamicSharedMemorySize, DSMEM_BYTES);

    float* grh = nullptr;
    cudaGetSymbolAddress((void**)&grh, g_rh);

    split_s_kernel<<<8192, 256>>>(S0, S1);
    build_inp_kernel<<<512, 256>>>(inp);

    const dim3 gG(NCOLS / NT, NNODES / MT, 2);   // (33, 4, 2)

    for (int pass = 0; pass < 2; pass++) {
        build_h_kernel<<<dim3(16, 64), 256>>>(pass == 0 ? hx : grh);
        // xs1 = S0@X0 -> XT1 ; xs3 = S1@X0 -> XT3
        gemm_mma<false><<<gG, 512, DSMEM_BYTES>>>(0, 0, 1);
        // xs2 = 2*S0@XT1 - X0 -> XT2 ; xs4 = 2*S1@XT3 - X0 -> XT4
        gemm_mma<true><<<gG, 512, DSMEM_BYTES>>>(1, 2, 2);

        if (pass == 0)
            proj1_kernel<<<dim3(16, 64), 256>>>(Wo, bo, hx);
        else
            proj2_kernel<<<dim3(16, 64), 256>>>(Wu, bu, hx, out);
    }
}

// round 9
// speedup vs baseline: 2.3297x; 1.3434x over previous
#include <cuda_runtime.h>
#include <cuda_bf16.h>
#include <cstdint>
#include <math.h>

// ---------------- Problem constants ----------------
#define BDIM   64
#define NNODES 1024
#define UDIM   64
#define NCOLS  4224          // 66 features * 64 batch
#define NM     5
#define XTSZ   (NCOLS * NNODES)

// Diffusion GEMM tiling (R7 proven config)
#define MT 128
#define NT 128
#define KC 32
#define NCHUNK 32
#define ROWB 80
#define REG_BYTES (128 * ROWB)
#define OFF_AH 0
#define OFF_AL (1 * REG_BYTES)
#define OFF_BH (2 * REG_BYTES)
#define OFF_BL (3 * REG_BYTES)
#define STAGE_BYTES (4 * REG_BYTES)   // 40960
#define DSMEM_BYTES (2 * STAGE_BYTES) // 81920

// ---------------- Device scratch ----------------
__device__ __align__(256) __nv_bfloat16 g_XTh[NM][XTSZ];
__device__ __align__(256) __nv_bfloat16 g_XTl[NM][XTSZ];
__device__ __align__(256) __nv_bfloat16 g_Sh[2][1024 * 1024];
__device__ __align__(256) __nv_bfloat16 g_Sl[2][1024 * 1024];
__device__ __align__(256) __nv_bfloat16 g_Woh[330 * 128];
__device__ __align__(256) __nv_bfloat16 g_Wol[330 * 128];
__device__ __align__(256) __nv_bfloat16 g_Wuh[330 * 64];
__device__ __align__(256) __nv_bfloat16 g_Wul[330 * 64];
__device__ __align__(256) float g_rh[BDIM * NNODES * UDIM];
__device__ __align__(256) float g_u [BDIM * NNODES * UDIM];

// ---------------- helpers ----------------
__device__ __forceinline__ uint32_t smem_u32(const void* p) {
    uint32_t a;
    asm("{ .reg .u64 t; cvta.to.shared.u64 t, %1; cvt.u32.u64 %0, t; }" : "=r"(a) : "l"(p));
    return a;
}
__device__ __forceinline__ void cp16(uint32_t saddr, const void* gaddr) {
    asm volatile("cp.async.cg.shared.global [%0], [%1], 16;" :: "r"(saddr), "l"(gaddr));
}
__device__ __forceinline__ void cp16z(uint32_t saddr, const void* gaddr, uint32_t srcsize) {
    asm volatile("cp.async.cg.shared.global [%0], [%1], 16, %2;"
                 :: "r"(saddr), "l"(gaddr), "r"(srcsize));
}
__device__ __forceinline__ void ldmx4(uint32_t& r0, uint32_t& r1, uint32_t& r2, uint32_t& r3,
                                      uint32_t addr) {
    asm volatile("ldmatrix.sync.aligned.m8n8.x4.shared.b16 {%0,%1,%2,%3}, [%4];"
                 : "=r"(r0), "=r"(r1), "=r"(r2), "=r"(r3) : "r"(addr));
}
__device__ __forceinline__ void ldmx4t(uint32_t* r, uint32_t addr) {
    asm volatile("ldmatrix.sync.aligned.m8n8.x4.trans.shared.b16 {%0,%1,%2,%3}, [%4];"
                 : "=r"(r[0]), "=r"(r[1]), "=r"(r[2]), "=r"(r[3]) : "r"(addr));
}
__device__ __forceinline__ void mma16816(float* c, const uint32_t* a, uint32_t b0, uint32_t b1) {
    asm volatile(
        "mma.sync.aligned.m16n8k16.row.col.f32.bf16.bf16.f32 "
        "{%0,%1,%2,%3}, {%4,%5,%6,%7}, {%8,%9}, {%0,%1,%2,%3};"
        : "+f"(c[0]), "+f"(c[1]), "+f"(c[2]), "+f"(c[3])
        : "r"(a[0]), "r"(a[1]), "r"(a[2]), "r"(a[3]), "r"(b0), "r"(b1));
}

// ============================================================================
// splits
// ============================================================================
__global__ void split_s_kernel(const float* __restrict__ S0, const float* __restrict__ S1) {
    int idx = blockIdx.x * 256 + threadIdx.x;
    int z = idx >> 20;
    int e = idx & 1048575;
    float v = (z ? S1 : S0)[e];
    __nv_bfloat16 h = __float2bfloat16(v);
    g_Sh[z][e] = h;
    g_Sl[z][e] = __float2bfloat16(v - __bfloat162float(h));
}

__global__ void split_w_kernel(const float* __restrict__ Wo, const float* __restrict__ Wu) {
    int idx = blockIdx.x * 256 + threadIdx.x;   // 63360 total
    if (idx < 42240) {
        float v = Wo[idx];
        __nv_bfloat16 h = __float2bfloat16(v);
        g_Woh[idx] = h;
        g_Wol[idx] = __float2bfloat16(v - __bfloat162float(h));
    } else if (idx < 63360) {
        int e = idx - 42240;
        float v = Wu[e];
        __nv_bfloat16 h = __float2bfloat16(v);
        g_Wuh[e] = h;
        g_Wul[e] = __float2bfloat16(v - __bfloat162float(h));
    }
}

// build XT0 input rows c in [0,128)
__global__ void build_inp_kernel(const float* __restrict__ inp) {
    int idx = blockIdx.x * 256 + threadIdx.x;           // 128*1024
    int c = idx >> 10, i = idx & 1023;
    int f = c >> 6, b = c & 63;
    float v = inp[b * 2048 + i * 2 + f];
    __nv_bfloat16 h = __float2bfloat16(v);
    g_XTh[0][c * 1024 + i] = h;
    g_XTl[0][c * 1024 + i] = __float2bfloat16(v - __bfloat162float(h));
}

// build XT0 hidden rows via smem transpose (coalesced both sides)
__global__ __launch_bounds__(256)
void build_h_kernel(const float* __restrict__ hsrc) {
    __shared__ float T[64][65];
    const int i0 = blockIdx.x * 64;
    const int b  = blockIdx.y;
    const int tid = threadIdx.x;
    {
        const int u = tid & 63;
        const int iib = tid >> 6;
#pragma unroll
        for (int w = 0; w < 16; ++w) {
            const int ii = iib + w * 4;
            T[u][ii] = hsrc[(size_t)b * 65536 + (size_t)(i0 + ii) * 64 + u];
        }
    }
    __syncthreads();
    {
        const int ii = tid & 63;
        const int ub = tid >> 6;
#pragma unroll
        for (int w = 0; w < 16; ++w) {
            const int u = ub + w * 4;
            float v = T[u][ii];
            __nv_bfloat16 h = __float2bfloat16(v);
            const size_t off = (size_t)((u + 2) * 64 + b) * 1024 + i0 + ii;
            g_XTh[0][off] = h;
            g_XTl[0][off] = __float2bfloat16(v - __bfloat162float(h));
        }
    }
}

// ============================================================================
// bf16x3 mma.sync diffusion GEMM (R7 config): C = S[z] @ X[mi] (CHEB: 2C - X0)
// grid (33, 8, 2), 256 threads.
// ============================================================================
template <bool CHEB>
__global__ __launch_bounds__(256)
void gemm_mma(int inBase, int inStride, int outBase) {
    const int z = blockIdx.z;
    const int it = blockIdx.y, jt = blockIdx.x;
    const int mi_idx = inBase + z * inStride;
    const int mo = outBase + 2 * z;

    const __nv_bfloat16* __restrict__ Ah = g_Sh[z];
    const __nv_bfloat16* __restrict__ Al = g_Sl[z];
    const __nv_bfloat16* __restrict__ Bh = g_XTh[mi_idx];
    const __nv_bfloat16* __restrict__ Bl = g_XTl[mi_idx];
    __nv_bfloat16* __restrict__ Ch = g_XTh[mo];
    __nv_bfloat16* __restrict__ Cl = g_XTl[mo];

    extern __shared__ char sm[];
    const uint32_t sb0 = smem_u32(sm);

    const int tid = threadIdx.x;
    const int warp = tid >> 5;
    const int lane = tid & 31;
    const int wm = warp >> 2;
    const int wn = warp & 3;

    const size_t arow0 = (size_t)(it * MT) * 1024;
    const size_t brow0 = (size_t)(jt * NT) * 1024;

    const uint32_t a_lm = (uint32_t)((lane & 15) * ROWB + ((lane >> 4) << 4));
    const uint32_t b_lm = (uint32_t)((((lane >> 4) << 3) + (lane & 7)) * ROWB +
                                     (((lane >> 3) & 1) << 4));

    float acc[4][4][4];
#pragma unroll
    for (int i = 0; i < 4; i++)
#pragma unroll
        for (int j = 0; j < 4; j++)
#pragma unroll
            for (int r = 0; r < 4; r++) acc[i][j][r] = 0.f;

    auto issue = [&](int c) {
        const int buf = c & 1;
        const int k0 = c * KC;
        const uint32_t sbase = sb0 + buf * STAGE_BYTES;
#pragma unroll
        for (int q = 0; q < 8; q++) {
            int idx = tid + q * 256;
            int region = idx >> 9;
            int row = (idx >> 2) & 127;
            int seg = idx & 3;
            const __nv_bfloat16* gp;
            if (region == 0)      gp = Ah + arow0;
            else if (region == 1) gp = Al + arow0;
            else if (region == 2) gp = Bh + brow0;
            else                  gp = Bl + brow0;
            gp += (size_t)row * 1024 + k0 + seg * 8;
            cp16(sbase + region * REG_BYTES + row * ROWB + seg * 16, gp);
        }
        asm volatile("cp.async.commit_group;" ::: "memory");
    };

    issue(0);

    for (int c = 0; c < NCHUNK; ++c) {
        if (c + 1 < NCHUNK) {
            issue(c + 1);
            asm volatile("cp.async.wait_group 1;" ::: "memory");
        } else {
            asm volatile("cp.async.wait_group 0;" ::: "memory");
        }
        __syncthreads();

        const uint32_t sbase = sb0 + (c & 1) * STAGE_BYTES;
        const uint32_t aB = sbase + a_lm + (uint32_t)(wm * 64) * ROWB;
        const uint32_t bB = sbase + b_lm + (uint32_t)(wn * 32) * ROWB;

#pragma unroll
        for (int s = 0; s < 2; ++s) {
            const uint32_t ks = (uint32_t)(s << 5);
            uint32_t bh[2][4], bl[2][4];
#pragma unroll
            for (int p = 0; p < 2; ++p) {
                ldmx4(bh[p][0], bh[p][1], bh[p][2], bh[p][3],
                      bB + OFF_BH + (uint32_t)(p * 16) * ROWB + ks);
                ldmx4(bl[p][0], bl[p][1], bl[p][2], bl[p][3],
                      bB + OFF_BL + (uint32_t)(p * 16) * ROWB + ks);
            }
#pragma unroll
            for (int mi = 0; mi < 4; ++mi) {
                uint32_t ah[4], al[4];
                ldmx4(ah[0], ah[1], ah[2], ah[3],
                      aB + OFF_AH + (uint32_t)(mi * 16) * ROWB + ks);
                ldmx4(al[0], al[1], al[2], al[3],
                      aB + OFF_AL + (uint32_t)(mi * 16) * ROWB + ks);
#pragma unroll
                for (int nj = 0; nj < 4; ++nj) {
                    const int p = nj >> 1, h = (nj & 1) << 1;
                    mma16816(acc[mi][nj], ah, bh[p][h], bh[p][h + 1]);
                    mma16816(acc[mi][nj], ah, bl[p][h], bl[p][h + 1]);
                    mma16816(acc[mi][nj], al, bh[p][h], bh[p][h + 1]);
                }
            }
        }
        __syncthreads();
    }

    // epilogue: stride-133 smem transpose; scalar stores (odd stride, 8B traps)
    float* Csm = (float*)sm;
    const int gid = lane >> 2;
    const int tig = lane & 3;
#pragma unroll
    for (int mi = 0; mi < 4; ++mi) {
#pragma unroll
        for (int nj = 0; nj < 4; ++nj) {
            const int r0 = wm * 64 + mi * 16 + gid;
            const int n = wn * 32 + nj * 8 + 2 * tig;
            Csm[r0 * 133 + n]           = acc[mi][nj][0];
            Csm[r0 * 133 + n + 1]       = acc[mi][nj][1];
            Csm[(r0 + 8) * 133 + n]     = acc[mi][nj][2];
            Csm[(r0 + 8) * 133 + n + 1] = acc[mi][nj][3];
        }
    }
    __syncthreads();

#pragma unroll 1
    for (int iter = 0; iter < 16; ++iter) {
        const int j = iter * 8 + warp;
        const size_t jg = (size_t)(jt * NT + j);
#pragma unroll
        for (int q = 0; q < 4; ++q) {
            const int i = lane + q * 32;
            const size_t ig = (size_t)(it * MT) + i;
            float y = Csm[i * 133 + j];
            if (CHEB) {
                float x0 = __bfloat162float(g_XTh[0][jg * 1024 + ig]) +
                           __bfloat162float(g_XTl[0][jg * 1024 + ig]);
                y = 2.f * y - x0;
            }
            __nv_bfloat16 h = __float2bfloat16(y);
            Ch[jg * 1024 + ig] = h;
            Cl[jg * 1024 + ig] = __float2bfloat16(y - __bfloat162float(h));
        }
    }
}

// ============================================================================
// Tensor-core projection: Y^T[o][n] = sum_k W[k][o] * A[k][n]  (k = f*5+m)
// A[k][n] = XT_m[f*64+b][n] (n contiguous). Both operands via ldmatrix.trans.
// K = 330 zero-padded to 336 (21 chunks of 16) via cp.async zfill.
// IS_P1: sigmoid gates -> g_rh (r*hx), g_u.   else: tanh cand + GRU combine.
// ============================================================================
template <int OUT, int NTILE, int PX, int PW, int PY, bool IS_P1>
__global__ __launch_bounds__(256)
void proj_mma(const __nv_bfloat16* __restrict__ Wh, const __nv_bfloat16* __restrict__ Wl,
              const float* __restrict__ bias, const float* __restrict__ hx,
              float* __restrict__ outp) {
    constexpr int XSEG = NTILE / 8;
    constexpr int WSEG = OUT / 8;
    constexpr int OFF_XH = 0;
    constexpr int OFF_XL = 16 * PX;
    constexpr int OFF_WH = 32 * PX;
    constexpr int OFF_WL = 32 * PX + 16 * PW;
    constexpr int STAGE  = 32 * (PX + PW);
    constexpr int NQ = (4 * NTILE + 4 * OUT) / 256;
    constexpr int NCK = 21;
    constexpr int WN_CNT = NTILE / 32;

    const int n0 = blockIdx.x * NTILE;
    const int b  = blockIdx.y;

    extern __shared__ char sm[];
    const uint32_t sb0 = smem_u32(sm);

    const int tid = threadIdx.x;
    const int warp = tid >> 5;
    const int lane = tid & 31;
    const int wm = warp / WN_CNT;
    const int wn = warp % WN_CNT;

    // trans ldmatrix lane maps (derived from fragment layouts)
    const uint32_t a_lmT = (uint32_t)(((lane & 7) + ((lane >> 4) & 1) * 8) * PW +
                                      (((lane >> 3) & 1) << 4));
    const uint32_t b_lmT = (uint32_t)(((lane & 7) + ((lane >> 3) & 1) * 8) * PX +
                                      ((lane >> 4) << 4));

    float acc[4][4][4];
#pragma unroll
    for (int i = 0; i < 4; i++)
#pragma unroll
        for (int j = 0; j < 4; j++)
#pragma unroll
            for (int r = 0; r < 4; r++) acc[i][j][r] = 0.f;

    const __nv_bfloat16* Xh0 = &g_XTh[0][0];
    const __nv_bfloat16* Xl0 = &g_XTl[0][0];

    auto issue = [&](int c) {
        const uint32_t sbase = sb0 + (c & 1) * STAGE;
        const int k0 = c * 16;
#pragma unroll
        for (int q = 0; q < NQ; q++) {
            int idx = tid + q * 256;
            if (idx < 4 * NTILE) {
                const int xsel = (idx >= 2 * NTILE);
                const int li = idx - xsel * 2 * NTILE;
                const int row = li / XSEG, seg = li % XSEG;
                const int k = k0 + row;
                const uint32_t sz = (k < 330) ? 16u : 0u;
                const int kk = (k < 330) ? k : 0;
                const int f = kk / 5, m = kk - f * 5;
                const __nv_bfloat16* src = (xsel ? Xl0 : Xh0) + (size_t)m * XTSZ +
                                           (size_t)(f * 64 + b) * 1024 + n0 + seg * 8;
                cp16z(sbase + (xsel ? OFF_XL : OFF_XH) + row * PX + seg * 16, src, sz);
            } else {
                const int wi = idx - 4 * NTILE;
                const int wsel = (wi >= 2 * OUT);
                const int li = wi - wsel * 2 * OUT;
                const int row = li / WSEG, seg = li % WSEG;
                const int k = k0 + row;
                const uint32_t sz = (k < 330) ? 16u : 0u;
                const int kk = (k < 330) ? k : 0;
                const __nv_bfloat16* src = (wsel ? Wl : Wh) + kk * OUT + seg * 8;
                cp16z(sbase + (wsel ? OFF_WL : OFF_WH) + row * PW + seg * 16, src, sz);
            }
        }
        asm volatile("cp.async.commit_group;" ::: "memory");
    };

    issue(0);

    for (int c = 0; c < NCK; ++c) {
        if (c + 1 < NCK) {
            issue(c + 1);
            asm volatile("cp.async.wait_group 1;" ::: "memory");
        } else {
            asm volatile("cp.async.wait_group 0;" ::: "memory");
        }
        __syncthreads();

        const uint32_t sbase = sb0 + (c & 1) * STAGE;
        uint32_t bh[2][4], bl[2][4];
#pragma unroll
        for (int p = 0; p < 2; ++p) {
            const uint32_t boff = (uint32_t)((wn * 32 + p * 16) * 2);
            ldmx4t(bh[p], sbase + OFF_XH + b_lmT + boff);
            ldmx4t(bl[p], sbase + OFF_XL + b_lmT + boff);
        }
#pragma unroll
        for (int mi = 0; mi < 4; ++mi) {
            const uint32_t aoff = (uint32_t)((wm * 64 + mi * 16) * 2);
            uint32_t ah[4], al[4];
            ldmx4t(ah, sbase + OFF_WH + a_lmT + aoff);
            ldmx4t(al, sbase + OFF_WL + a_lmT + aoff);
#pragma unroll
            for (int nj = 0; nj < 4; ++nj) {
                const int p = nj >> 1, h = (nj & 1) << 1;
                mma16816(acc[mi][nj], ah, bh[p][h], bh[p][h + 1]);
                mma16816(acc[mi][nj], ah, bl[p][h], bl[p][h + 1]);
                mma16816(acc[mi][nj], al, bh[p][h], bh[p][h + 1]);
            }
        }
        __syncthreads();
    }

    // stage Y^T[o][n] in smem (odd pitch PY -> conflict-free; scalar stores)
    float* Ysm = (float*)sm;
    const int gid = lane >> 2;
    const int tig = lane & 3;
#pragma unroll
    for (int mi = 0; mi < 4; ++mi) {
#pragma unroll
        for (int nj = 0; nj < 4; ++nj) {
            const int o0 = wm * 64 + mi * 16 + gid;
            const int n = wn * 32 + nj * 8 + 2 * tig;
            Ysm[o0 * PY + n]           = acc[mi][nj][0];
            Ysm[o0 * PY + n + 1]       = acc[mi][nj][1];
            Ysm[(o0 + 8) * PY + n]     = acc[mi][nj][2];
            Ysm[(o0 + 8) * PY + n + 1] = acc[mi][nj][3];
        }
    }
    __syncthreads();

    const int o = tid & 63;
    const int nb = tid >> 6;
    if (IS_P1) {
        const float b0 = bias[o];
        const float b1 = bias[o + 64];
#pragma unroll 1
        for (int it = 0; it < NTILE / 4; ++it) {
            const int n = nb + it * 4;
            const size_t idx = (size_t)b * 65536 + (size_t)(n0 + n) * 64 + o;
            const float r = 1.f / (1.f + expf(-(Ysm[o * PY + n] + b0)));
            const float u = 1.f / (1.f + expf(-(Ysm[(o + 64) * PY + n] + b1)));
            g_rh[idx] = r * hx[idx];
            g_u[idx]  = u;
        }
    } else {
        const float b0 = bias[o];
#pragma unroll 1
        for (int it = 0; it < NTILE / 4; ++it) {
            const int n = nb + it * 4;
            const size_t idx = (size_t)b * 65536 + (size_t)(n0 + n) * 64 + o;
            const float cc = tanhf(Ysm[o * PY + n] + b0);
            const float u = g_u[idx], h = hx[idx];
            outp[idx] = u * h + (1.f - u) * cc;
        }
    }
}

// ============================================================================
// Host driver
// ============================================================================
extern "C" void kernel_launch(void* const* d_in, const int* in_sizes, int n_in,
                              void* d_out, int out_size) {
    const float* inp = (const float*)d_in[0];
    const float* hx  = (const float*)d_in[1];
    const float* S0  = (const float*)d_in[2];
    const float* S1  = (const float*)d_in[3];
    const float* Wo  = (const float*)d_in[4];
    const float* bo  = (const float*)d_in[5];
    const float* Wu  = (const float*)d_in[6];
    const float* bu  = (const float*)d_in[7];
    float* out = (float*)d_out;

    // proj templates: <OUT, NTILE, PX, PW, PY, IS_P1>
    auto* p1 = proj_mma<128, 128, 272, 272, 129, true>;
    auto* p2 = proj_mma<64, 256, 528, 144, 257, false>;
    const int P1_SMEM = 128 * 129 * 4;   // 66048 (> 2*17408 pipeline)
    const int P2_SMEM = 64 * 257 * 4 > 2 * 21504 ? 64 * 257 * 4 : 2 * 21504;

    cudaFuncSetAttribute(gemm_mma<false>, cudaFuncAttributeMaxDynamicSharedMemorySize, DSMEM_BYTES);
    cudaFuncSetAttribute(gemm_mma<true>,  cudaFuncAttributeMaxDynamicSharedMemorySize, DSMEM_BYTES);
    cudaFuncSetAttribute(p1, cudaFuncAttributeMaxDynamicSharedMemorySize, P1_SMEM);
    cudaFuncSetAttribute(p2, cudaFuncAttributeMaxDynamicSharedMemorySize, P2_SMEM);

    float* grh = nullptr;
    cudaGetSymbolAddress((void**)&grh, g_rh);
    __nv_bfloat16 *gWoh = nullptr, *gWol = nullptr, *gWuh = nullptr, *gWul = nullptr;
    cudaGetSymbolAddress((void**)&gWoh, g_Woh);
    cudaGetSymbolAddress((void**)&gWol, g_Wol);
    cudaGetSymbolAddress((void**)&gWuh, g_Wuh);
    cudaGetSymbolAddress((void**)&gWul, g_Wul);

    split_s_kernel<<<8192, 256>>>(S0, S1);
    split_w_kernel<<<248, 256>>>(Wo, Wu);
    build_inp_kernel<<<512, 256>>>(inp);

    const dim3 gG(NCOLS / NT, NNODES / MT, 2);   // (33, 8, 2)

    for (int pass = 0; pass < 2; pass++) {
        build_h_kernel<<<dim3(16, 64), 256>>>(pass == 0 ? hx : grh);
        gemm_mma<false><<<gG, 256, DSMEM_BYTES>>>(0, 0, 1);
        gemm_mma<true><<<gG, 256, DSMEM_BYTES>>>(1, 2, 2);

        if (pass == 0)
            p1<<<dim3(8, 64), 256, P1_SMEM>>>(gWoh, gWol, bo, hx, nullptr);
        else
            p2<<<dim3(4, 64), 256, P2_SMEM>>>(gWuh, gWul, bu, hx, out);
    }
}

// round 10
// speedup vs baseline: 2.4069x; 1.0331x over previous
#include <cuda_runtime.h>
#include <cuda_bf16.h>
#include <cstdint>
#include <math.h>

// ---------------- Problem constants ----------------
#define BDIM   64
#define NNODES 1024
#define UDIM   64
#define NCOLS  4224          // 66 features * 64 batch
#define NM     6             // slots: 0=X0(pass1), 1..4 diffusion, 5=X0(pass2)
#define XTSZ   (NCOLS * NNODES)

// Diffusion GEMM tiling
#define MT 128
#define NT 128
#define KC 32
#define NCHUNK 32
#define ROWB 80
#define REG_BYTES (128 * ROWB)
#define OFF_AH 0
#define OFF_AL (1 * REG_BYTES)
#define OFF_BH (2 * REG_BYTES)
#define OFF_BL (3 * REG_BYTES)
#define STAGE_BYTES (4 * REG_BYTES)   // 40960
#define DSMEM_BYTES (2 * STAGE_BYTES) // 81920

// ---------------- Device scratch ----------------
__device__ __align__(256) __nv_bfloat16 g_XTh[NM][XTSZ];
__device__ __align__(256) __nv_bfloat16 g_XTl[NM][XTSZ];
__device__ __align__(256) __nv_bfloat16 g_Sh[2][1024 * 1024];
__device__ __align__(256) __nv_bfloat16 g_Sl[2][1024 * 1024];
__device__ __align__(256) __nv_bfloat16 g_Woh[330 * 128];
__device__ __align__(256) __nv_bfloat16 g_Wol[330 * 128];
__device__ __align__(256) __nv_bfloat16 g_Wuh[330 * 64];
__device__ __align__(256) __nv_bfloat16 g_Wul[330 * 64];
__device__ __align__(256) float g_u[BDIM * NNODES * UDIM];

// ---------------- helpers ----------------
__device__ __forceinline__ uint32_t smem_u32(const void* p) {
    uint32_t a;
    asm("{ .reg .u64 t; cvta.to.shared.u64 t, %1; cvt.u32.u64 %0, t; }" : "=r"(a) : "l"(p));
    return a;
}
__device__ __forceinline__ void cp16(uint32_t saddr, const void* gaddr) {
    asm volatile("cp.async.cg.shared.global [%0], [%1], 16;" :: "r"(saddr), "l"(gaddr));
}
__device__ __forceinline__ void cp16z(uint32_t saddr, const void* gaddr, uint32_t srcsize) {
    asm volatile("cp.async.cg.shared.global [%0], [%1], 16, %2;"
                 :: "r"(saddr), "l"(gaddr), "r"(srcsize));
}
__device__ __forceinline__ void ldmx4a(uint32_t* r, uint32_t addr) {
    asm volatile("ldmatrix.sync.aligned.m8n8.x4.shared.b16 {%0,%1,%2,%3}, [%4];"
                 : "=r"(r[0]), "=r"(r[1]), "=r"(r[2]), "=r"(r[3]) : "r"(addr));
}
__device__ __forceinline__ void ldmx4t(uint32_t* r, uint32_t addr) {
    asm volatile("ldmatrix.sync.aligned.m8n8.x4.trans.shared.b16 {%0,%1,%2,%3}, [%4];"
                 : "=r"(r[0]), "=r"(r[1]), "=r"(r[2]), "=r"(r[3]) : "r"(addr));
}
__device__ __forceinline__ void mma16816(float* c, const uint32_t* a, uint32_t b0, uint32_t b1) {
    asm volatile(
        "mma.sync.aligned.m16n8k16.row.col.f32.bf16.bf16.f32 "
        "{%0,%1,%2,%3}, {%4,%5,%6,%7}, {%8,%9}, {%0,%1,%2,%3};"
        : "+f"(c[0]), "+f"(c[1]), "+f"(c[2]), "+f"(c[3])
        : "r"(a[0]), "r"(a[1]), "r"(a[2]), "r"(a[3]), "r"(b0), "r"(b1));
}

// ============================================================================
// splits / builders
// ============================================================================
__global__ void split_s_kernel(const float* __restrict__ S0, const float* __restrict__ S1) {
    int idx = blockIdx.x * 256 + threadIdx.x;
    int z = idx >> 20;
    int e = idx & 1048575;
    float v = (z ? S1 : S0)[e];
    __nv_bfloat16 h = __float2bfloat16(v);
    g_Sh[z][e] = h;
    g_Sl[z][e] = __float2bfloat16(v - __bfloat162float(h));
}

__global__ void split_w_kernel(const float* __restrict__ Wo, const float* __restrict__ Wu) {
    int idx = blockIdx.x * 256 + threadIdx.x;
    if (idx < 42240) {
        float v = Wo[idx];
        __nv_bfloat16 h = __float2bfloat16(v);
        g_Woh[idx] = h;
        g_Wol[idx] = __float2bfloat16(v - __bfloat162float(h));
    } else if (idx < 63360) {
        int e = idx - 42240;
        float v = Wu[e];
        __nv_bfloat16 h = __float2bfloat16(v);
        g_Wuh[e] = h;
        g_Wul[e] = __float2bfloat16(v - __bfloat162float(h));
    }
}

// input rows c in [0,128) -> slots 0 AND 5 (identical across passes)
__global__ void build_inp_kernel(const float* __restrict__ inp) {
    int idx = blockIdx.x * 256 + threadIdx.x;           // 128*1024
    int c = idx >> 10, i = idx & 1023;
    int f = c >> 6, b = c & 63;
    float v = inp[b * 2048 + i * 2 + f];
    __nv_bfloat16 h = __float2bfloat16(v);
    __nv_bfloat16 l = __float2bfloat16(v - __bfloat162float(h));
    g_XTh[0][c * 1024 + i] = h;
    g_XTl[0][c * 1024 + i] = l;
    g_XTh[5][c * 1024 + i] = h;
    g_XTl[5][c * 1024 + i] = l;
}

// hidden rows from hx (pass 1 only) via smem transpose
__global__ __launch_bounds__(256)
void build_h_kernel(const float* __restrict__ hsrc) {
    __shared__ float T[64][65];
    const int i0 = blockIdx.x * 64;
    const int b  = blockIdx.y;
    const int tid = threadIdx.x;
    {
        const int u = tid & 63;
        const int iib = tid >> 6;
#pragma unroll
        for (int w = 0; w < 16; ++w) {
            const int ii = iib + w * 4;
            T[u][ii] = hsrc[(size_t)b * 65536 + (size_t)(i0 + ii) * 64 + u];
        }
    }
    __syncthreads();
    {
        const int ii = tid & 63;
        const int ub = tid >> 6;
#pragma unroll
        for (int w = 0; w < 16; ++w) {
            const int u = ub + w * 4;
            float v = T[u][ii];
            __nv_bfloat16 h = __float2bfloat16(v);
            const size_t off = (size_t)((u + 2) * 64 + b) * 1024 + i0 + ii;
            g_XTh[0][off] = h;
            g_XTl[0][off] = __float2bfloat16(v - __bfloat162float(h));
        }
    }
}

// ============================================================================
// bf16x3 mma.sync diffusion GEMM, grid (33,8,2), 256 threads.
// All 12 LDSM per chunk hoisted (B both k-steps preloaded, A ping-pong).
// ============================================================================
template <bool CHEB>
__global__ __launch_bounds__(256)
void gemm_mma(int inBase, int inStride, int outBase, int x0Idx) {
    const int z = blockIdx.z;
    const int it = blockIdx.y, jt = blockIdx.x;
    const int mi_idx = inBase + z * inStride;
    const int mo = outBase + 2 * z;

    const __nv_bfloat16* __restrict__ Ah = g_Sh[z];
    const __nv_bfloat16* __restrict__ Al = g_Sl[z];
    const __nv_bfloat16* __restrict__ Bh = g_XTh[mi_idx];
    const __nv_bfloat16* __restrict__ Bl = g_XTl[mi_idx];
    __nv_bfloat16* __restrict__ Ch = g_XTh[mo];
    __nv_bfloat16* __restrict__ Cl = g_XTl[mo];
    const __nv_bfloat16* __restrict__ X0h = g_XTh[x0Idx];
    const __nv_bfloat16* __restrict__ X0l = g_XTl[x0Idx];

    extern __shared__ char sm[];
    const uint32_t sb0 = smem_u32(sm);

    const int tid = threadIdx.x;
    const int warp = tid >> 5;
    const int lane = tid & 31;
    const int wm = warp >> 2;
    const int wn = warp & 3;

    const size_t arow0 = (size_t)(it * MT) * 1024;
    const size_t brow0 = (size_t)(jt * NT) * 1024;

    const uint32_t a_lm = (uint32_t)((lane & 15) * ROWB + ((lane >> 4) << 4));
    const uint32_t b_lm = (uint32_t)((((lane >> 4) << 3) + (lane & 7)) * ROWB +
                                     (((lane >> 3) & 1) << 4));

    float acc[4][4][4];
#pragma unroll
    for (int i = 0; i < 4; i++)
#pragma unroll
        for (int j = 0; j < 4; j++)
#pragma unroll
            for (int r = 0; r < 4; r++) acc[i][j][r] = 0.f;

    auto issue = [&](int c) {
        const int buf = c & 1;
        const int k0 = c * KC;
        const uint32_t sbase = sb0 + buf * STAGE_BYTES;
#pragma unroll
        for (int q = 0; q < 8; q++) {
            int idx = tid + q * 256;
            int region = idx >> 9;
            int row = (idx >> 2) & 127;
            int seg = idx & 3;
            const __nv_bfloat16* gp;
            if (region == 0)      gp = Ah + arow0;
            else if (region == 1) gp = Al + arow0;
            else if (region == 2) gp = Bh + brow0;
            else                  gp = Bl + brow0;
            gp += (size_t)row * 1024 + k0 + seg * 8;
            cp16(sbase + region * REG_BYTES + row * ROWB + seg * 16, gp);
        }
        asm volatile("cp.async.commit_group;" ::: "memory");
    };

    issue(0);

    for (int c = 0; c < NCHUNK; ++c) {
        if (c + 1 < NCHUNK) {
            issue(c + 1);
            asm volatile("cp.async.wait_group 1;" ::: "memory");
        } else {
            asm volatile("cp.async.wait_group 0;" ::: "memory");
        }
        __syncthreads();

        const uint32_t sbase = sb0 + (c & 1) * STAGE_BYTES;
        const uint32_t aB = sbase + a_lm + (uint32_t)(wm * 64) * ROWB;
        const uint32_t bB = sbase + b_lm + (uint32_t)(wn * 32) * ROWB;

        // preload ALL B fragments (both k-steps)
        uint32_t bh[2][2][4], bl[2][2][4];
#pragma unroll
        for (int s = 0; s < 2; ++s) {
            const uint32_t ks = (uint32_t)(s << 5);
#pragma unroll
            for (int p = 0; p < 2; ++p) {
                ldmx4a(bh[s][p], bB + OFF_BH + (uint32_t)(p * 16) * ROWB + ks);
                ldmx4a(bl[s][p], bB + OFF_BL + (uint32_t)(p * 16) * ROWB + ks);
            }
        }
        // A ping-pong
        uint32_t aF[2][2][4];
        ldmx4a(aF[0][0], aB + OFF_AH);
        ldmx4a(aF[0][1], aB + OFF_AL);
#pragma unroll
        for (int g = 0; g < 8; ++g) {
            const int s = g >> 2, mi = g & 3;
            const int cur = g & 1, nxt = cur ^ 1;
            if (g < 7) {
                const int g2 = g + 1;
                const uint32_t ao = (uint32_t)((g2 & 3) * 16) * ROWB +
                                    (uint32_t)((g2 >> 2) << 5);
                ldmx4a(aF[nxt][0], aB + OFF_AH + ao);
                ldmx4a(aF[nxt][1], aB + OFF_AL + ao);
            }
#pragma unroll
            for (int nj = 0; nj < 4; ++nj) {
                const int p = nj >> 1, h = (nj & 1) << 1;
                mma16816(acc[mi][nj], aF[cur][0], bh[s][p][h], bh[s][p][h + 1]);
                mma16816(acc[mi][nj], aF[cur][0], bl[s][p][h], bl[s][p][h + 1]);
                mma16816(acc[mi][nj], aF[cur][1], bh[s][p][h], bh[s][p][h + 1]);
            }
        }
        __syncthreads();
    }

    // epilogue: stride-133 smem transpose; scalar stores (odd stride, 8B traps)
    float* Csm = (float*)sm;
    const int gid = lane >> 2;
    const int tig = lane & 3;
#pragma unroll
    for (int mi = 0; mi < 4; ++mi) {
#pragma unroll
        for (int nj = 0; nj < 4; ++nj) {
            const int r0 = wm * 64 + mi * 16 + gid;
            const int n = wn * 32 + nj * 8 + 2 * tig;
            Csm[r0 * 133 + n]           = acc[mi][nj][0];
            Csm[r0 * 133 + n + 1]       = acc[mi][nj][1];
            Csm[(r0 + 8) * 133 + n]     = acc[mi][nj][2];
            Csm[(r0 + 8) * 133 + n + 1] = acc[mi][nj][3];
        }
    }
    __syncthreads();

#pragma unroll 1
    for (int iter = 0; iter < 16; ++iter) {
        const int j = iter * 8 + warp;
        const size_t jg = (size_t)(jt * NT + j);
#pragma unroll
        for (int q = 0; q < 4; ++q) {
            const int i = lane + q * 32;
            const size_t ig = (size_t)(it * MT) + i;
            float y = Csm[i * 133 + j];
            if (CHEB) {
                float x0 = __bfloat162float(X0h[jg * 1024 + ig]) +
                           __bfloat162float(X0l[jg * 1024 + ig]);
                y = 2.f * y - x0;
            }
            __nv_bfloat16 h = __float2bfloat16(y);
            Ch[jg * 1024 + ig] = h;
            Cl[jg * 1024 + ig] = __float2bfloat16(y - __bfloat162float(h));
        }
    }
}

// ============================================================================
// Tensor-core projection (K=330 padded to 336).
// IS_P1: r -> XT slot 5 hidden rows (bf16 hi/lo) fused, u -> g_u.
// else : c = tanh(.), out = u*hx + (1-u)*c.
// ============================================================================
template <int OUT, int NTILE, int PX, int PW, int PY, bool IS_P1>
__global__ __launch_bounds__(256)
void proj_mma(const __nv_bfloat16* __restrict__ Wh, const __nv_bfloat16* __restrict__ Wl,
              const float* __restrict__ bias, const float* __restrict__ hx,
              float* __restrict__ outp, int x0slot) {
    constexpr int XSEG = NTILE / 8;
    constexpr int WSEG = OUT / 8;
    constexpr int OFF_XH = 0;
    constexpr int OFF_XL = 16 * PX;
    constexpr int OFF_WH = 32 * PX;
    constexpr int OFF_WL = 32 * PX + 16 * PW;
    constexpr int STAGE  = 32 * (PX + PW);
    constexpr int NQ = (4 * NTILE + 4 * OUT) / 256;
    constexpr int NCK = 21;
    constexpr int WN_CNT = NTILE / 32;

    const int n0 = blockIdx.x * NTILE;
    const int b  = blockIdx.y;

    extern __shared__ char sm[];
    const uint32_t sb0 = smem_u32(sm);

    const int tid = threadIdx.x;
    const int warp = tid >> 5;
    const int lane = tid & 31;
    const int wm = warp / WN_CNT;
    const int wn = warp % WN_CNT;

    const uint32_t a_lmT = (uint32_t)(((lane & 7) + ((lane >> 4) & 1) * 8) * PW +
                                      (((lane >> 3) & 1) << 4));
    const uint32_t b_lmT = (uint32_t)(((lane & 7) + ((lane >> 3) & 1) * 8) * PX +
                                      ((lane >> 4) << 4));

    float acc[4][4][4];
#pragma unroll
    for (int i = 0; i < 4; i++)
#pragma unroll
        for (int j = 0; j < 4; j++)
#pragma unroll
            for (int r = 0; r < 4; r++) acc[i][j][r] = 0.f;

    const __nv_bfloat16* Xh0 = &g_XTh[0][0];
    const __nv_bfloat16* Xl0 = &g_XTl[0][0];

    auto issue = [&](int c) {
        const uint32_t sbase = sb0 + (c & 1) * STAGE;
        const int k0 = c * 16;
#pragma unroll
        for (int q = 0; q < NQ; q++) {
            int idx = tid + q * 256;
            if (idx < 4 * NTILE) {
                const int xsel = (idx >= 2 * NTILE);
                const int li = idx - xsel * 2 * NTILE;
                const int row = li / XSEG, seg = li % XSEG;
                const int k = k0 + row;
                const uint32_t sz = (k < 330) ? 16u : 0u;
                const int kk = (k < 330) ? k : 0;
                const int f = kk / 5, m = kk - f * 5;
                const int mslot = (m == 0) ? x0slot : m;
                const __nv_bfloat16* src = (xsel ? Xl0 : Xh0) + (size_t)mslot * XTSZ +
                                           (size_t)(f * 64 + b) * 1024 + n0 + seg * 8;
                cp16z(sbase + (xsel ? OFF_XL : OFF_XH) + row * PX + seg * 16, src, sz);
            } else {
                const int wi = idx - 4 * NTILE;
                const int wsel = (wi >= 2 * OUT);
                const int li = wi - wsel * 2 * OUT;
                const int row = li / WSEG, seg = li % WSEG;
                const int k = k0 + row;
                const uint32_t sz = (k < 330) ? 16u : 0u;
                const int kk = (k < 330) ? k : 0;
                const __nv_bfloat16* src = (wsel ? Wl : Wh) + kk * OUT + seg * 8;
                cp16z(sbase + (wsel ? OFF_WL : OFF_WH) + row * PW + seg * 16, src, sz);
            }
        }
        asm volatile("cp.async.commit_group;" ::: "memory");
    };

    issue(0);

    for (int c = 0; c < NCK; ++c) {
        if (c + 1 < NCK) {
            issue(c + 1);
            asm volatile("cp.async.wait_group 1;" ::: "memory");
        } else {
            asm volatile("cp.async.wait_group 0;" ::: "memory");
        }
        __syncthreads();

        const uint32_t sbase = sb0 + (c & 1) * STAGE;
        uint32_t bh[2][4], bl[2][4];
#pragma unroll
        for (int p = 0; p < 2; ++p) {
            const uint32_t boff = (uint32_t)((wn * 32 + p * 16) * 2);
            ldmx4t(bh[p], sbase + OFF_XH + b_lmT + boff);
            ldmx4t(bl[p], sbase + OFF_XL + b_lmT + boff);
        }
#pragma unroll
        for (int mi = 0; mi < 4; ++mi) {
            const uint32_t aoff = (uint32_t)((wm * 64 + mi * 16) * 2);
            uint32_t ah[4], al[4];
            ldmx4t(ah, sbase + OFF_WH + a_lmT + aoff);
            ldmx4t(al, sbase + OFF_WL + a_lmT + aoff);
#pragma unroll
            for (int nj = 0; nj < 4; ++nj) {
                const int p = nj >> 1, h = (nj & 1) << 1;
                mma16816(acc[mi][nj], ah, bh[p][h], bh[p][h + 1]);
                mma16816(acc[mi][nj], ah, bl[p][h], bl[p][h + 1]);
                mma16816(acc[mi][nj], al, bh[p][h], bh[p][h + 1]);
            }
        }
        __syncthreads();
    }

    // stage Y^T[o][n] in smem (odd pitch PY -> conflict-free; scalar stores)
    float* Ysm = (float*)sm;
    const int gid = lane >> 2;
    const int tig = lane & 3;
#pragma unroll
    for (int mi = 0; mi < 4; ++mi) {
#pragma unroll
        for (int nj = 0; nj < 4; ++nj) {
            const int o0 = wm * 64 + mi * 16 + gid;
            const int n = wn * 32 + nj * 8 + 2 * tig;
            Ysm[o0 * PY + n]           = acc[mi][nj][0];
            Ysm[o0 * PY + n + 1]       = acc[mi][nj][1];
            Ysm[(o0 + 8) * PY + n]     = acc[mi][nj][2];
            Ysm[(o0 + 8) * PY + n + 1] = acc[mi][nj][3];
        }
    }

    if (IS_P1) {
        // hx tile -> smem (coalesced), placed after Ysm
        float* Hsm = (float*)(sm + OUT * PY * 4);
        {
            const int o = tid & 63;
            const int ng = tid >> 6;
#pragma unroll
            for (int w = 0; w < NTILE / 4; ++w) {
                const int n = ng + w * 4;
                Hsm[n * 65 + o] = hx[(size_t)b * 65536 + (size_t)(n0 + n) * 64 + o];
            }
        }
        __syncthreads();
        // part A: rh = sigmoid(Y[o][n]+b0) * hx -> XT slot 5 hidden rows (n-coalesced)
        {
            const int n = tid & 127;
            const int og = tid >> 7;            // 0..1
#pragma unroll 1
            for (int ow = 0; ow < 32; ++ow) {
                const int o = og * 32 + ow;
                const float r = 1.f / (1.f + expf(-(Ysm[o * PY + n] + bias[o])));
                const float v = r * Hsm[n * 65 + o];
                __nv_bfloat16 h = __float2bfloat16(v);
                const size_t off = (size_t)((o + 2) * 64 + b) * 1024 + n0 + n;
                g_XTh[5][off] = h;
                g_XTl[5][off] = __float2bfloat16(v - __bfloat162float(h));
            }
        }
        // part B: u -> g_u (o-coalesced)
        {
            const int o = tid & 63;
            const int ng = tid >> 6;
            const float b1 = bias[o + 64];
#pragma unroll 1
            for (int w = 0; w < NTILE / 4; ++w) {
                const int n = ng + w * 4;
                const float u = 1.f / (1.f + expf(-(Ysm[(o + 64) * PY + n] + b1)));
                g_u[(size_t)b * 65536 + (size_t)(n0 + n) * 64 + o] = u;
            }
        }
    } else {
        __syncthreads();
        const int o = tid & 63;
        const int nb = tid >> 6;
        const float b0 = bias[o];
#pragma unroll 1
        for (int it = 0; it < NTILE / 4; ++it) {
            const int n = nb + it * 4;
            const size_t idx = (size_t)b * 65536 + (size_t)(n0 + n) * 64 + o;
            const float cc = tanhf(Ysm[o * PY + n] + b0);
            const float u = g_u[idx], h = hx[idx];
            outp[idx] = u * h + (1.f - u) * cc;
        }
    }
}

// ============================================================================
// Host driver
// ============================================================================
extern "C" void kernel_launch(void* const* d_in, const int* in_sizes, int n_in,
                              void* d_out, int out_size) {
    const float* inp = (const float*)d_in[0];
    const float* hx  = (const float*)d_in[1];
    const float* S0  = (const float*)d_in[2];
    const float* S1  = (const float*)d_in[3];
    const float* Wo  = (const float*)d_in[4];
    const float* bo  = (const float*)d_in[5];
    const float* Wu  = (const float*)d_in[6];
    const float* bu  = (const float*)d_in[7];
    float* out = (float*)d_out;

    auto* p1 = proj_mma<128, 128, 272, 272, 129, true>;
    auto* p2 = proj_mma<64, 256, 528, 144, 257, false>;
    const int P1_SMEM = 128 * 129 * 4 + 128 * 65 * 4;   // Ysm + Hsm = 99328
    const int P2_SMEM = 64 * 257 * 4;                   // 65792 (> pipeline 43008)

    cudaFuncSetAttribute(gemm_mma<false>, cudaFuncAttributeMaxDynamicSharedMemorySize, DSMEM_BYTES);
    cudaFuncSetAttribute(gemm_mma<true>,  cudaFuncAttributeMaxDynamicSharedMemorySize, DSMEM_BYTES);
    cudaFuncSetAttribute(p1, cudaFuncAttributeMaxDynamicSharedMemorySize, P1_SMEM);
    cudaFuncSetAttribute(p2, cudaFuncAttributeMaxDynamicSharedMemorySize, P2_SMEM);

    __nv_bfloat16 *gWoh = nullptr, *gWol = nullptr, *gWuh = nullptr, *gWul = nullptr;
    cudaGetSymbolAddress((void**)&gWoh, g_Woh);
    cudaGetSymbolAddress((void**)&gWol, g_Wol);
    cudaGetSymbolAddress((void**)&gWuh, g_Wuh);
    cudaGetSymbolAddress((void**)&gWul, g_Wul);

    split_s_kernel<<<8192, 256>>>(S0, S1);
    split_w_kernel<<<248, 256>>>(Wo, Wu);
    build_inp_kernel<<<512, 256>>>(inp);
    build_h_kernel<<<dim3(16, 64), 256>>>(hx);

    const dim3 gG(NCOLS / NT, NNODES / MT, 2);   // (33, 8, 2)

    // pass 1 (X0 = slot 0)
    gemm_mma<false><<<gG, 256, DSMEM_BYTES>>>(0, 0, 1, 0);
    gemm_mma<true><<<gG, 256, DSMEM_BYTES>>>(1, 2, 2, 0);
    p1<<<dim3(8, 64), 256, P1_SMEM>>>(gWoh, gWol, bo, hx, nullptr, 0);

    // pass 2 (X0 = slot 5, written by p1 + build_inp)
    gemm_mma<false><<<gG, 256, DSMEM_BYTES>>>(5, 0, 1, 5);
    gemm_mma<true><<<gG, 256, DSMEM_BYTES>>>(1, 2, 2, 5);
    p2<<<dim3(4, 64), 256, P2_SMEM>>>(gWuh, gWul, bu, hx, out, 5);
}

// round 11
// speedup vs baseline: 3.1985x; 1.3289x over previous
#include <cuda_runtime.h>
#include <cuda_fp16.h>
#include <cstdint>
#include <math.h>

// ---------------- Problem constants ----------------
#define BDIM   64
#define NNODES 1024
#define UDIM   64
#define NCOLS  4224          // 66 features * 64 batch
#define NM     6             // slots: 0=X0(pass1), 1..4 diffusion, 5=X0(pass2)
#define XTSZ   (NCOLS * NNODES)

// Diffusion GEMM tiling (fp16x2: A single, B hi/lo)
#define MT 128
#define NT 128
#define KC 32
#define NCHUNK 32
#define ROWB 80
#define REG_BYTES (128 * ROWB)        // 10240
#define OFF_A  0
#define OFF_BH (1 * REG_BYTES)
#define OFF_BL (2 * REG_BYTES)
#define STAGE_BYTES (3 * REG_BYTES)   // 30720
#define DSMEM_BYTES 68096             // max(2*30720, epilogue 128*133*4)

// ---------------- Device scratch ----------------
__device__ __align__(256) __half g_XTh[NM][XTSZ];
__device__ __align__(256) __half g_XTl[NM][XTSZ];
__device__ __align__(256) __half g_S16[2][1024 * 1024];
__device__ __align__(256) __half g_Wo16[330 * 128];
__device__ __align__(256) __half g_Wu16[330 * 64];
__device__ __align__(256) float g_u[BDIM * NNODES * UDIM];

// ---------------- helpers ----------------
__device__ __forceinline__ uint32_t smem_u32(const void* p) {
    uint32_t a;
    asm("{ .reg .u64 t; cvta.to.shared.u64 t, %1; cvt.u32.u64 %0, t; }" : "=r"(a) : "l"(p));
    return a;
}
__device__ __forceinline__ void cp16(uint32_t saddr, const void* gaddr) {
    asm volatile("cp.async.cg.shared.global [%0], [%1], 16;" :: "r"(saddr), "l"(gaddr));
}
__device__ __forceinline__ void cp16z(uint32_t saddr, const void* gaddr, uint32_t srcsize) {
    asm volatile("cp.async.cg.shared.global [%0], [%1], 16, %2;"
                 :: "r"(saddr), "l"(gaddr), "r"(srcsize));
}
__device__ __forceinline__ void ldmx4a(uint32_t* r, uint32_t addr) {
    asm volatile("ldmatrix.sync.aligned.m8n8.x4.shared.b16 {%0,%1,%2,%3}, [%4];"
                 : "=r"(r[0]), "=r"(r[1]), "=r"(r[2]), "=r"(r[3]) : "r"(addr));
}
__device__ __forceinline__ void ldmx4t(uint32_t* r, uint32_t addr) {
    asm volatile("ldmatrix.sync.aligned.m8n8.x4.trans.shared.b16 {%0,%1,%2,%3}, [%4];"
                 : "=r"(r[0]), "=r"(r[1]), "=r"(r[2]), "=r"(r[3]) : "r"(addr));
}
__device__ __forceinline__ void mmaf16(float* c, const uint32_t* a, uint32_t b0, uint32_t b1) {
    asm volatile(
        "mma.sync.aligned.m16n8k16.row.col.f32.f16.f16.f32 "
        "{%0,%1,%2,%3}, {%4,%5,%6,%7}, {%8,%9}, {%0,%1,%2,%3};"
        : "+f"(c[0]), "+f"(c[1]), "+f"(c[2]), "+f"(c[3])
        : "r"(a[0]), "r"(a[1]), "r"(a[2]), "r"(a[3]), "r"(b0), "r"(b1));
}
__device__ __forceinline__ void split16(float v, __half& h, __half& l) {
    h = __float2half(v);
    l = __float2half(v - __half2float(h));
}

// ============================================================================
// splits / builders
// ============================================================================
__global__ void split_s_kernel(const float* __restrict__ S0, const float* __restrict__ S1) {
    int idx = blockIdx.x * 256 + threadIdx.x;       // 2M total
    int z = idx >> 20;
    int e = idx & 1048575;
    g_S16[z][e] = __float2half((z ? S1 : S0)[e]);
}

__global__ void split_w_kernel(const float* __restrict__ Wo, const float* __restrict__ Wu) {
    int idx = blockIdx.x * 256 + threadIdx.x;
    if (idx < 42240)       g_Wo16[idx] = __float2half(Wo[idx]);
    else if (idx < 63360)  g_Wu16[idx - 42240] = __float2half(Wu[idx - 42240]);
}

// input rows c in [0,128) -> slots 0 AND 5
__global__ void build_inp_kernel(const float* __restrict__ inp) {
    int idx = blockIdx.x * 256 + threadIdx.x;           // 128*1024
    int c = idx >> 10, i = idx & 1023;
    int f = c >> 6, b = c & 63;
    __half h, l;
    split16(inp[b * 2048 + i * 2 + f], h, l);
    g_XTh[0][c * 1024 + i] = h;
    g_XTl[0][c * 1024 + i] = l;
    g_XTh[5][c * 1024 + i] = h;
    g_XTl[5][c * 1024 + i] = l;
}

// hidden rows from hx (pass 1) via smem transpose
__global__ __launch_bounds__(256)
void build_h_kernel(const float* __restrict__ hsrc) {
    __shared__ float T[64][65];
    const int i0 = blockIdx.x * 64;
    const int b  = blockIdx.y;
    const int tid = threadIdx.x;
    {
        const int u = tid & 63;
        const int iib = tid >> 6;
#pragma unroll
        for (int w = 0; w < 16; ++w) {
            const int ii = iib + w * 4;
            T[u][ii] = hsrc[(size_t)b * 65536 + (size_t)(i0 + ii) * 64 + u];
        }
    }
    __syncthreads();
    {
        const int ii = tid & 63;
        const int ub = tid >> 6;
#pragma unroll
        for (int w = 0; w < 16; ++w) {
            const int u = ub + w * 4;
            __half h, l;
            split16(T[u][ii], h, l);
            const size_t off = (size_t)((u + 2) * 64 + b) * 1024 + i0 + ii;
            g_XTh[0][off] = h;
            g_XTl[0][off] = l;
        }
    }
}

// ============================================================================
// fp16x2 mma.sync diffusion GEMM: C = S[z] @ X[mi]  (CHEB: 2C - X0)
// grid (33, 8, 2), 256 threads. Regions: A(single), Bh, Bl.
// ============================================================================
template <bool CHEB>
__global__ __launch_bounds__(256)
void gemm_mma(int inBase, int inStride, int outBase, int x0Idx) {
    const int z = blockIdx.z;
    const int it = blockIdx.y, jt = blockIdx.x;
    const int mi_idx = inBase + z * inStride;
    const int mo = outBase + 2 * z;

    const __half* __restrict__ Am = g_S16[z];
    const __half* __restrict__ Bh = g_XTh[mi_idx];
    const __half* __restrict__ Bl = g_XTl[mi_idx];
    __half* __restrict__ Ch = g_XTh[mo];
    __half* __restrict__ Cl = g_XTl[mo];
    const __half* __restrict__ X0h = g_XTh[x0Idx];
    const __half* __restrict__ X0l = g_XTl[x0Idx];

    extern __shared__ char sm[];
    const uint32_t sb0 = smem_u32(sm);

    const int tid = threadIdx.x;
    const int warp = tid >> 5;
    const int lane = tid & 31;
    const int wm = warp >> 2;
    const int wn = warp & 3;

    const size_t arow0 = (size_t)(it * MT) * 1024;
    const size_t brow0 = (size_t)(jt * NT) * 1024;

    const uint32_t a_lm = (uint32_t)((lane & 15) * ROWB + ((lane >> 4) << 4));
    const uint32_t b_lm = (uint32_t)((((lane >> 4) << 3) + (lane & 7)) * ROWB +
                                     (((lane >> 3) & 1) << 4));

    float acc[4][4][4];
#pragma unroll
    for (int i = 0; i < 4; i++)
#pragma unroll
        for (int j = 0; j < 4; j++)
#pragma unroll
            for (int r = 0; r < 4; r++) acc[i][j][r] = 0.f;

    // stage loader: 1536 cp.async of 16B, 6 per thread
    auto issue = [&](int c) {
        const int buf = c & 1;
        const int k0 = c * KC;
        const uint32_t sbase = sb0 + buf * STAGE_BYTES;
#pragma unroll
        for (int q = 0; q < 6; q++) {
            int idx = tid + q * 256;
            int region = idx >> 9;             // 0..2
            int row = (idx >> 2) & 127;
            int seg = idx & 3;
            const __half* gp;
            if (region == 0)      gp = Am + arow0;
            else if (region == 1) gp = Bh + brow0;
            else                  gp = Bl + brow0;
            gp += (size_t)row * 1024 + k0 + seg * 8;
            cp16(sbase + region * REG_BYTES + row * ROWB + seg * 16, gp);
        }
        asm volatile("cp.async.commit_group;" ::: "memory");
    };

    issue(0);

    for (int c = 0; c < NCHUNK; ++c) {
        if (c + 1 < NCHUNK) {
            issue(c + 1);
            asm volatile("cp.async.wait_group 1;" ::: "memory");
        } else {
            asm volatile("cp.async.wait_group 0;" ::: "memory");
        }
        __syncthreads();

        const uint32_t sbase = sb0 + (c & 1) * STAGE_BYTES;
        const uint32_t aB = sbase + a_lm + (uint32_t)(wm * 64) * ROWB;
        const uint32_t bB = sbase + b_lm + (uint32_t)(wn * 32) * ROWB;

        // preload ALL B fragments (both k-steps, hi+lo)
        uint32_t bh[2][2][4], bl[2][2][4];
#pragma unroll
        for (int s = 0; s < 2; ++s) {
            const uint32_t ks = (uint32_t)(s << 5);
#pragma unroll
            for (int p = 0; p < 2; ++p) {
                ldmx4a(bh[s][p], bB + OFF_BH + (uint32_t)(p * 16) * ROWB + ks);
                ldmx4a(bl[s][p], bB + OFF_BL + (uint32_t)(p * 16) * ROWB + ks);
            }
        }
        // A ping-pong (single precision term)
        uint32_t aF[2][4];
        ldmx4a(aF[0], aB + OFF_A);
#pragma unroll
        for (int g = 0; g < 8; ++g) {
            const int s = g >> 2, mi = g & 3;
            const int cur = g & 1;
            if (g < 7) {
                const int g2 = g + 1;
                const uint32_t ao = (uint32_t)((g2 & 3) * 16) * ROWB +
                                    (uint32_t)((g2 >> 2) << 5);
                ldmx4a(aF[cur ^ 1], aB + OFF_A + ao);
            }
#pragma unroll
            for (int nj = 0; nj < 4; ++nj) {
                const int p = nj >> 1, h = (nj & 1) << 1;
                mmaf16(acc[mi][nj], aF[cur], bh[s][p][h], bh[s][p][h + 1]);
                mmaf16(acc[mi][nj], aF[cur], bl[s][p][h], bl[s][p][h + 1]);
            }
        }
        __syncthreads();
    }

    // epilogue: stride-133 smem transpose; scalar stores (odd stride, 8B traps)
    float* Csm = (float*)sm;
    const int gid = lane >> 2;
    const int tig = lane & 3;
#pragma unroll
    for (int mi = 0; mi < 4; ++mi) {
#pragma unroll
        for (int nj = 0; nj < 4; ++nj) {
            const int r0 = wm * 64 + mi * 16 + gid;
            const int n = wn * 32 + nj * 8 + 2 * tig;
            Csm[r0 * 133 + n]           = acc[mi][nj][0];
            Csm[r0 * 133 + n + 1]       = acc[mi][nj][1];
            Csm[(r0 + 8) * 133 + n]     = acc[mi][nj][2];
            Csm[(r0 + 8) * 133 + n + 1] = acc[mi][nj][3];
        }
    }
    __syncthreads();

#pragma unroll 1
    for (int iter = 0; iter < 16; ++iter) {
        const int j = iter * 8 + warp;
        const size_t jg = (size_t)(jt * NT + j);
#pragma unroll
        for (int q = 0; q < 4; ++q) {
            const int i = lane + q * 32;
            const size_t ig = (size_t)(it * MT) + i;
            float y = Csm[i * 133 + j];
            if (CHEB) {
                float x0 = __half2float(X0h[jg * 1024 + ig]) +
                           __half2float(X0l[jg * 1024 + ig]);
                y = 2.f * y - x0;
            }
            __half h, l;
            split16(y, h, l);
            Ch[jg * 1024 + ig] = h;
            Cl[jg * 1024 + ig] = l;
        }
    }
}

// ============================================================================
// Tensor-core projection (fp16x2: W single, X hi/lo). K=330 padded to 336.
// IS_P1: r -> XT slot 5 hidden rows fused, u -> g_u.
// else : c = tanh(.), out = u*hx + (1-u)*c.
// ============================================================================
template <int OUT, int NTILE, int PX, int PW, int PY, bool IS_P1>
__global__ __launch_bounds__(256)
void proj_mma(const __half* __restrict__ Wm, const float* __restrict__ bias,
              const float* __restrict__ hx, float* __restrict__ outp, int x0slot) {
    constexpr int XSEG = NTILE / 8;
    constexpr int WSEG = OUT / 8;
    constexpr int OFF_XH = 0;
    constexpr int OFF_XL = 16 * PX;
    constexpr int OFF_W  = 32 * PX;
    constexpr int STAGE  = 32 * PX + 16 * PW;
    constexpr int TOTAL = 4 * NTILE + 2 * OUT;
    constexpr int NQ = (TOTAL + 255) / 256;
    constexpr int NCK = 21;
    constexpr int WN_CNT = NTILE / 32;

    const int n0 = blockIdx.x * NTILE;
    const int b  = blockIdx.y;

    extern __shared__ char sm[];
    const uint32_t sb0 = smem_u32(sm);

    const int tid = threadIdx.x;
    const int warp = tid >> 5;
    const int lane = tid & 31;
    const int wm = warp / WN_CNT;
    const int wn = warp % WN_CNT;

    const uint32_t a_lmT = (uint32_t)(((lane & 7) + ((lane >> 4) & 1) * 8) * PW +
                                      (((lane >> 3) & 1) << 4));
    const uint32_t b_lmT = (uint32_t)(((lane & 7) + ((lane >> 3) & 1) * 8) * PX +
                                      ((lane >> 4) << 4));

    float acc[4][4][4];
#pragma unroll
    for (int i = 0; i < 4; i++)
#pragma unroll
        for (int j = 0; j < 4; j++)
#pragma unroll
            for (int r = 0; r < 4; r++) acc[i][j][r] = 0.f;

    const __half* Xh0 = &g_XTh[0][0];
    const __half* Xl0 = &g_XTl[0][0];

    auto issue = [&](int c) {
        const uint32_t sbase = sb0 + (c & 1) * STAGE;
        const int k0 = c * 16;
#pragma unroll
        for (int q = 0; q < NQ; q++) {
            int idx = tid + q * 256;
            if (idx >= TOTAL) break;
            if (idx < 4 * NTILE) {
                const int xsel = (idx >= 2 * NTILE);
                const int li = idx - xsel * 2 * NTILE;
                const int row = li / XSEG, seg = li % XSEG;
                const int k = k0 + row;
                const uint32_t sz = (k < 330) ? 16u : 0u;
                const int kk = (k < 330) ? k : 0;
                const int f = kk / 5, m = kk - f * 5;
                const int mslot = (m == 0) ? x0slot : m;
                const __half* src = (xsel ? Xl0 : Xh0) + (size_t)mslot * XTSZ +
                                    (size_t)(f * 64 + b) * 1024 + n0 + seg * 8;
                cp16z(sbase + (xsel ? OFF_XL : OFF_XH) + row * PX + seg * 16, src, sz);
            } else {
                const int li = idx - 4 * NTILE;
                const int row = li / WSEG, seg = li % WSEG;
                const int k = k0 + row;
                const uint32_t sz = (k < 330) ? 16u : 0u;
                const int kk = (k < 330) ? k : 0;
                cp16z(sbase + OFF_W + row * PW + seg * 16, Wm + kk * OUT + seg * 8, sz);
            }
        }
        asm volatile("cp.async.commit_group;" ::: "memory");
    };

    issue(0);

    for (int c = 0; c < NCK; ++c) {
        if (c + 1 < NCK) {
            issue(c + 1);
            asm volatile("cp.async.wait_group 1;" ::: "memory");
        } else {
            asm volatile("cp.async.wait_group 0;" ::: "memory");
        }
        __syncthreads();

        const uint32_t sbase = sb0 + (c & 1) * STAGE;
        uint32_t bh[2][4], bl[2][4];
#pragma unroll
        for (int p = 0; p < 2; ++p) {
            const uint32_t boff = (uint32_t)((wn * 32 + p * 16) * 2);
            ldmx4t(bh[p], sbase + OFF_XH + b_lmT + boff);
            ldmx4t(bl[p], sbase + OFF_XL + b_lmT + boff);
        }
#pragma unroll
        for (int mi = 0; mi < 4; ++mi) {
            const uint32_t aoff = (uint32_t)((wm * 64 + mi * 16) * 2);
            uint32_t aw[4];
            ldmx4t(aw, sbase + OFF_W + a_lmT + aoff);
#pragma unroll
            for (int nj = 0; nj < 4; ++nj) {
                const int p = nj >> 1, h = (nj & 1) << 1;
                mmaf16(acc[mi][nj], aw, bh[p][h], bh[p][h + 1]);
                mmaf16(acc[mi][nj], aw, bl[p][h], bl[p][h + 1]);
            }
        }
        __syncthreads();
    }

    // stage Y^T[o][n] in smem (odd pitch PY; scalar stores)
    float* Ysm = (float*)sm;
    const int gid = lane >> 2;
    const int tig = lane & 3;
#pragma unroll
    for (int mi = 0; mi < 4; ++mi) {
#pragma unroll
        for (int nj = 0; nj < 4; ++nj) {
            const int o0 = wm * 64 + mi * 16 + gid;
            const int n = wn * 32 + nj * 8 + 2 * tig;
            Ysm[o0 * PY + n]           = acc[mi][nj][0];
            Ysm[o0 * PY + n + 1]       = acc[mi][nj][1];
            Ysm[(o0 + 8) * PY + n]     = acc[mi][nj][2];
            Ysm[(o0 + 8) * PY + n + 1] = acc[mi][nj][3];
        }
    }

    if (IS_P1) {
        float* Hsm = (float*)(sm + OUT * PY * 4);
        {
            const int o = tid & 63;
            const int ng = tid >> 6;
#pragma unroll
            for (int w = 0; w < NTILE / 4; ++w) {
                const int n = ng + w * 4;
                Hsm[n * 65 + o] = hx[(size_t)b * 65536 + (size_t)(n0 + n) * 64 + o];
            }
        }
        __syncthreads();
        {   // rh = sigmoid(Y + b0) * hx -> XT slot 5 (n-coalesced)
            const int n = tid & 127;
            const int og = tid >> 7;
#pragma unroll 1
            for (int ow = 0; ow < 32; ++ow) {
                const int o = og * 32 + ow;
                const float r = 1.f / (1.f + expf(-(Ysm[o * PY + n] + bias[o])));
                const float v = r * Hsm[n * 65 + o];
                __half h, l;
                split16(v, h, l);
                const size_t off = (size_t)((o + 2) * 64 + b) * 1024 + n0 + n;
                g_XTh[5][off] = h;
                g_XTl[5][off] = l;
            }
        }
        {   // u -> g_u (o-coalesced)
            const int o = tid & 63;
            const int ng = tid >> 6;
            const float b1 = bias[o + 64];
#pragma unroll 1
            for (int w = 0; w < NTILE / 4; ++w) {
                const int n = ng + w * 4;
                const float u = 1.f / (1.f + expf(-(Ysm[(o + 64) * PY + n] + b1)));
                g_u[(size_t)b * 65536 + (size_t)(n0 + n) * 64 + o] = u;
            }
        }
    } else {
        __syncthreads();
        const int o = tid & 63;
        const int nb = tid >> 6;
        const float b0 = bias[o];
#pragma unroll 1
        for (int it = 0; it < NTILE / 4; ++it) {
            const int n = nb + it * 4;
            const size_t idx = (size_t)b * 65536 + (size_t)(n0 + n) * 64 + o;
            const float cc = tanhf(Ysm[o * PY + n] + b0);
            const float u = g_u[idx], h = hx[idx];
            outp[idx] = u * h + (1.f - u) * cc;
        }
    }
}

// ============================================================================
// Host driver
// ============================================================================
extern "C" void kernel_launch(void* const* d_in, const int* in_sizes, int n_in,
                              void* d_out, int out_size) {
    const float* inp = (const float*)d_in[0];
    const float* hx  = (const float*)d_in[1];
    const float* S0  = (const float*)d_in[2];
    const float* S1  = (const float*)d_in[3];
    const float* Wo  = (const float*)d_in[4];
    const float* bo  = (const float*)d_in[5];
    const float* Wu  = (const float*)d_in[6];
    const float* bu  = (const float*)d_in[7];
    float* out = (float*)d_out;

    auto* p1 = proj_mma<128, 128, 272, 272, 129, true>;
    auto* p2 = proj_mma<64, 256, 528, 144, 257, false>;
    const int P1_SMEM = 128 * 129 * 4 + 128 * 65 * 4;   // 99328
    const int P2_SMEM = 64 * 257 * 4;                   // 65792

    cudaFuncSetAttribute(gemm_mma<false>, cudaFuncAttributeMaxDynamicSharedMemorySize, DSMEM_BYTES);
    cudaFuncSetAttribute(gemm_mma<true>,  cudaFuncAttributeMaxDynamicSharedMemorySize, DSMEM_BYTES);
    cudaFuncSetAttribute(p1, cudaFuncAttributeMaxDynamicSharedMemorySize, P1_SMEM);
    cudaFuncSetAttribute(p2, cudaFuncAttributeMaxDynamicSharedMemorySize, P2_SMEM);

    __half *gWo = nullptr, *gWu = nullptr;
    cudaGetSymbolAddress((void**)&gWo, g_Wo16);
    cudaGetSymbolAddress((void**)&gWu, g_Wu16);

    split_s_kernel<<<8192, 256>>>(S0, S1);
    split_w_kernel<<<248, 256>>>(Wo, Wu);
    build_inp_kernel<<<512, 256>>>(inp);
    build_h_kernel<<<dim3(16, 64), 256>>>(hx);

    const dim3 gG(NCOLS / NT, NNODES / MT, 2);   // (33, 8, 2)

    // pass 1 (X0 = slot 0)
    gemm_mma<false><<<gG, 256, DSMEM_BYTES>>>(0, 0, 1, 0);
    gemm_mma<true><<<gG, 256, DSMEM_BYTES>>>(1, 2, 2, 0);
    p1<<<dim3(8, 64), 256, P1_SMEM>>>(gWo, bo, hx, nullptr, 0);

    // pass 2 (X0 = slot 5, written by p1 + build_inp)
    gemm_mma<false><<<gG, 256, DSMEM_BYTES>>>(5, 0, 1, 5);
    gemm_mma<true><<<gG, 256, DSMEM_BYTES>>>(1, 2, 2, 5);
    p2<<<dim3(4, 64), 256, P2_SMEM>>>(gWu, bu, hx, out, 5);
}

// round 12
// speedup vs baseline: 4.3893x; 1.3723x over previous
#include <cuda_runtime.h>
#include <cuda_fp16.h>
#include <cstdint>
#include <math.h>

// ---------------- Problem constants ----------------
#define BDIM   64
#define NNODES 1024
#define UDIM   64
#define NCOLS  4224          // 66 features * 64 batch
#define NM     6             // slots: 0=X0(pass1), 1..4 diffusion, 5=X0(pass2)
#define XTSZ   (NCOLS * NNODES)

// Diffusion GEMM tiling (fp16x1: A single, B single(hi); epilogue exact X0)
#define MT 128
#define NT 128
#define KC 32
#define NCHUNK 32
#define ROWB 80
#define REG_BYTES (128 * ROWB)        // 10240
#define OFF_A  0
#define OFF_B  (1 * REG_BYTES)
#define STAGE_BYTES (2 * REG_BYTES)   // 20480
#define DSMEM_BYTES 68096             // max(2*20480, epilogue 128*133*4)

// ---------------- Device scratch ----------------
__device__ __align__(256) __half g_XTh[NM][XTSZ];
__device__ __align__(256) __half g_XTl[NM][XTSZ];
__device__ __align__(256) __half g_S16[2][1024 * 1024];
__device__ __align__(256) __half g_Wo16[330 * 128];
__device__ __align__(256) __half g_Wu16[330 * 64];
__device__ __align__(256) float g_u[BDIM * NNODES * UDIM];

// ---------------- helpers ----------------
__device__ __forceinline__ uint32_t smem_u32(const void* p) {
    uint32_t a;
    asm("{ .reg .u64 t; cvta.to.shared.u64 t, %1; cvt.u32.u64 %0, t; }" : "=r"(a) : "l"(p));
    return a;
}
__device__ __forceinline__ void cp16(uint32_t saddr, const void* gaddr) {
    asm volatile("cp.async.cg.shared.global [%0], [%1], 16;" :: "r"(saddr), "l"(gaddr));
}
__device__ __forceinline__ void cp16z(uint32_t saddr, const void* gaddr, uint32_t srcsize) {
    asm volatile("cp.async.cg.shared.global [%0], [%1], 16, %2;"
                 :: "r"(saddr), "l"(gaddr), "r"(srcsize));
}
__device__ __forceinline__ void ldmx4a(uint32_t* r, uint32_t addr) {
    asm volatile("ldmatrix.sync.aligned.m8n8.x4.shared.b16 {%0,%1,%2,%3}, [%4];"
                 : "=r"(r[0]), "=r"(r[1]), "=r"(r[2]), "=r"(r[3]) : "r"(addr));
}
__device__ __forceinline__ void ldmx4t(uint32_t* r, uint32_t addr) {
    asm volatile("ldmatrix.sync.aligned.m8n8.x4.trans.shared.b16 {%0,%1,%2,%3}, [%4];"
                 : "=r"(r[0]), "=r"(r[1]), "=r"(r[2]), "=r"(r[3]) : "r"(addr));
}
__device__ __forceinline__ void mmaf16(float* c, const uint32_t* a, uint32_t b0, uint32_t b1) {
    asm volatile(
        "mma.sync.aligned.m16n8k16.row.col.f32.f16.f16.f32 "
        "{%0,%1,%2,%3}, {%4,%5,%6,%7}, {%8,%9}, {%0,%1,%2,%3};"
        : "+f"(c[0]), "+f"(c[1]), "+f"(c[2]), "+f"(c[3])
        : "r"(a[0]), "r"(a[1]), "r"(a[2]), "r"(a[3]), "r"(b0), "r"(b1));
}
__device__ __forceinline__ void split16(float v, __half& h, __half& l) {
    h = __float2half(v);
    l = __float2half(v - __half2float(h));
}

// ============================================================================
// splits / builders
// ============================================================================
__global__ void split_s_kernel(const float* __restrict__ S0, const float* __restrict__ S1) {
    int idx = blockIdx.x * 256 + threadIdx.x;       // 2M total
    int z = idx >> 20;
    int e = idx & 1048575;
    g_S16[z][e] = __float2half((z ? S1 : S0)[e]);
}

__global__ void split_w_kernel(const float* __restrict__ Wo, const float* __restrict__ Wu) {
    int idx = blockIdx.x * 256 + threadIdx.x;
    if (idx < 42240)       g_Wo16[idx] = __float2half(Wo[idx]);
    else if (idx < 63360)  g_Wu16[idx - 42240] = __float2half(Wu[idx - 42240]);
}

// input rows c in [0,128) -> slots 0 AND 5
__global__ void build_inp_kernel(const float* __restrict__ inp) {
    int idx = blockIdx.x * 256 + threadIdx.x;           // 128*1024
    int c = idx >> 10, i = idx & 1023;
    int f = c >> 6, b = c & 63;
    __half h, l;
    split16(inp[b * 2048 + i * 2 + f], h, l);
    g_XTh[0][c * 1024 + i] = h;
    g_XTl[0][c * 1024 + i] = l;
    g_XTh[5][c * 1024 + i] = h;
    g_XTl[5][c * 1024 + i] = l;
}

// hidden rows from hx (pass 1) via smem transpose
__global__ __launch_bounds__(256)
void build_h_kernel(const float* __restrict__ hsrc) {
    __shared__ float T[64][65];
    const int i0 = blockIdx.x * 64;
    const int b  = blockIdx.y;
    const int tid = threadIdx.x;
    {
        const int u = tid & 63;
        const int iib = tid >> 6;
#pragma unroll
        for (int w = 0; w < 16; ++w) {
            const int ii = iib + w * 4;
            T[u][ii] = hsrc[(size_t)b * 65536 + (size_t)(i0 + ii) * 64 + u];
        }
    }
    __syncthreads();
    {
        const int ii = tid & 63;
        const int ub = tid >> 6;
#pragma unroll
        for (int w = 0; w < 16; ++w) {
            const int u = ub + w * 4;
            __half h, l;
            split16(T[u][ii], h, l);
            const size_t off = (size_t)((u + 2) * 64 + b) * 1024 + i0 + ii;
            g_XTh[0][off] = h;
            g_XTl[0][off] = l;
        }
    }
}

// ============================================================================
// fp16x1 mma.sync diffusion GEMM: C = S[z] @ X[mi]  (CHEB: 2C - X0 exact)
// grid (33, 8, 2), 256 threads. Regions: A, B (hi only). 32 MMA/warp/chunk.
// ============================================================================
template <bool CHEB>
__global__ __launch_bounds__(256)
void gemm_mma(int inBase, int inStride, int outBase, int x0Idx) {
    const int z = blockIdx.z;
    const int it = blockIdx.y, jt = blockIdx.x;
    const int mi_idx = inBase + z * inStride;
    const int mo = outBase + 2 * z;

    const __half* __restrict__ Am = g_S16[z];
    const __half* __restrict__ Bm = g_XTh[mi_idx];
    __half* __restrict__ Ch = g_XTh[mo];
    __half* __restrict__ Cl = g_XTl[mo];
    const __half* __restrict__ X0h = g_XTh[x0Idx];
    const __half* __restrict__ X0l = g_XTl[x0Idx];

    extern __shared__ char sm[];
    const uint32_t sb0 = smem_u32(sm);

    const int tid = threadIdx.x;
    const int warp = tid >> 5;
    const int lane = tid & 31;
    const int wm = warp >> 2;
    const int wn = warp & 3;

    const size_t arow0 = (size_t)(it * MT) * 1024;
    const size_t brow0 = (size_t)(jt * NT) * 1024;

    const uint32_t a_lm = (uint32_t)((lane & 15) * ROWB + ((lane >> 4) << 4));
    const uint32_t b_lm = (uint32_t)((((lane >> 4) << 3) + (lane & 7)) * ROWB +
                                     (((lane >> 3) & 1) << 4));

    float acc[4][4][4];
#pragma unroll
    for (int i = 0; i < 4; i++)
#pragma unroll
        for (int j = 0; j < 4; j++)
#pragma unroll
            for (int r = 0; r < 4; r++) acc[i][j][r] = 0.f;

    // stage loader: 1024 cp.async of 16B, 4 per thread
    auto issue = [&](int c) {
        const int buf = c & 1;
        const int k0 = c * KC;
        const uint32_t sbase = sb0 + buf * STAGE_BYTES;
#pragma unroll
        for (int q = 0; q < 4; q++) {
            int idx = tid + q * 256;
            int region = idx >> 9;             // 0..1
            int row = (idx >> 2) & 127;
            int seg = idx & 3;
            const __half* gp = region ? (Bm + brow0) : (Am + arow0);
            gp += (size_t)row * 1024 + k0 + seg * 8;
            cp16(sbase + region * REG_BYTES + row * ROWB + seg * 16, gp);
        }
        asm volatile("cp.async.commit_group;" ::: "memory");
    };

    issue(0);

    for (int c = 0; c < NCHUNK; ++c) {
        if (c + 1 < NCHUNK) {
            issue(c + 1);
            asm volatile("cp.async.wait_group 1;" ::: "memory");
        } else {
            asm volatile("cp.async.wait_group 0;" ::: "memory");
        }
        __syncthreads();

        const uint32_t sbase = sb0 + (c & 1) * STAGE_BYTES;
        const uint32_t aB = sbase + a_lm + (uint32_t)(wm * 64) * ROWB;
        const uint32_t bB = sbase + b_lm + (uint32_t)(wn * 32) * ROWB;

        // preload ALL B fragments (both k-steps)
        uint32_t bF[2][2][4];
#pragma unroll
        for (int s = 0; s < 2; ++s) {
            const uint32_t ks = (uint32_t)(s << 5);
#pragma unroll
            for (int p = 0; p < 2; ++p)
                ldmx4a(bF[s][p], bB + OFF_B + (uint32_t)(p * 16) * ROWB + ks);
        }
        // A ping-pong
        uint32_t aF[2][4];
        ldmx4a(aF[0], aB + OFF_A);
#pragma unroll
        for (int g = 0; g < 8; ++g) {
            const int s = g >> 2, mi = g & 3;
            const int cur = g & 1;
            if (g < 7) {
                const int g2 = g + 1;
                const uint32_t ao = (uint32_t)((g2 & 3) * 16) * ROWB +
                                    (uint32_t)((g2 >> 2) << 5);
                ldmx4a(aF[cur ^ 1], aB + OFF_A + ao);
            }
#pragma unroll
            for (int nj = 0; nj < 4; ++nj) {
                const int p = nj >> 1, h = (nj & 1) << 1;
                mmaf16(acc[mi][nj], aF[cur], bF[s][p][h], bF[s][p][h + 1]);
            }
        }
        __syncthreads();
    }

    // epilogue: stride-133 smem transpose; scalar stores (odd stride, 8B traps)
    float* Csm = (float*)sm;
    const int gid = lane >> 2;
    const int tig = lane & 3;
#pragma unroll
    for (int mi = 0; mi < 4; ++mi) {
#pragma unroll
        for (int nj = 0; nj < 4; ++nj) {
            const int r0 = wm * 64 + mi * 16 + gid;
            const int n = wn * 32 + nj * 8 + 2 * tig;
            Csm[r0 * 133 + n]           = acc[mi][nj][0];
            Csm[r0 * 133 + n + 1]       = acc[mi][nj][1];
            Csm[(r0 + 8) * 133 + n]     = acc[mi][nj][2];
            Csm[(r0 + 8) * 133 + n + 1] = acc[mi][nj][3];
        }
    }
    __syncthreads();

#pragma unroll 1
    for (int iter = 0; iter < 16; ++iter) {
        const int j = iter * 8 + warp;
        const size_t jg = (size_t)(jt * NT + j);
#pragma unroll
        for (int q = 0; q < 4; ++q) {
            const int i = lane + q * 32;
            const size_t ig = (size_t)(it * MT) + i;
            float y = Csm[i * 133 + j];
            if (CHEB) {
                float x0 = __half2float(X0h[jg * 1024 + ig]) +
                           __half2float(X0l[jg * 1024 + ig]);
                y = 2.f * y - x0;
            }
            __half h, l;
            split16(y, h, l);
            Ch[jg * 1024 + ig] = h;
            Cl[jg * 1024 + ig] = l;
        }
    }
}

// ============================================================================
// Tensor-core projection (fp16x2: W single, X hi/lo). K=330 padded to 336.
// IS_P1: r -> XT slot 5 hidden rows fused, u -> g_u.
// else : c = tanh(.), out = u*hx + (1-u)*c.
// ============================================================================
template <int OUT, int NTILE, int PX, int PW, int PY, bool IS_P1>
__global__ __launch_bounds__(256)
void proj_mma(const __half* __restrict__ Wm, const float* __restrict__ bias,
              const float* __restrict__ hx, float* __restrict__ outp, int x0slot) {
    constexpr int XSEG = NTILE / 8;
    constexpr int WSEG = OUT / 8;
    constexpr int OFF_XH = 0;
    constexpr int OFF_XL = 16 * PX;
    constexpr int OFF_W  = 32 * PX;
    constexpr int STAGE  = 32 * PX + 16 * PW;
    constexpr int TOTAL = 4 * NTILE + 2 * OUT;
    constexpr int NQ = (TOTAL + 255) / 256;
    constexpr int NCK = 21;
    constexpr int WN_CNT = NTILE / 32;

    const int n0 = blockIdx.x * NTILE;
    const int b  = blockIdx.y;

    extern __shared__ char sm[];
    const uint32_t sb0 = smem_u32(sm);

    const int tid = threadIdx.x;
    const int warp = tid >> 5;
    const int lane = tid & 31;
    const int wm = warp / WN_CNT;
    const int wn = warp % WN_CNT;

    const uint32_t a_lmT = (uint32_t)(((lane & 7) + ((lane >> 4) & 1) * 8) * PW +
                                      (((lane >> 3) & 1) << 4));
    const uint32_t b_lmT = (uint32_t)(((lane & 7) + ((lane >> 3) & 1) * 8) * PX +
                                      ((lane >> 4) << 4));

    float acc[4][4][4];
#pragma unroll
    for (int i = 0; i < 4; i++)
#pragma unroll
        for (int j = 0; j < 4; j++)
#pragma unroll
            for (int r = 0; r < 4; r++) acc[i][j][r] = 0.f;

    const __half* Xh0 = &g_XTh[0][0];
    const __half* Xl0 = &g_XTl[0][0];

    auto issue = [&](int c) {
        const uint32_t sbase = sb0 + (c & 1) * STAGE;
        const int k0 = c * 16;
#pragma unroll
        for (int q = 0; q < NQ; q++) {
            int idx = tid + q * 256;
            if (idx >= TOTAL) break;
            if (idx < 4 * NTILE) {
                const int xsel = (idx >= 2 * NTILE);
                const int li = idx - xsel * 2 * NTILE;
                const int row = li / XSEG, seg = li % XSEG;
                const int k = k0 + row;
                const uint32_t sz = (k < 330) ? 16u : 0u;
                const int kk = (k < 330) ? k : 0;
                const int f = kk / 5, m = kk - f * 5;
                const int mslot = (m == 0) ? x0slot : m;
                const __half* src = (xsel ? Xl0 : Xh0) + (size_t)mslot * XTSZ +
                                    (size_t)(f * 64 + b) * 1024 + n0 + seg * 8;
                cp16z(sbase + (xsel ? OFF_XL : OFF_XH) + row * PX + seg * 16, src, sz);
            } else {
                const int li = idx - 4 * NTILE;
                const int row = li / WSEG, seg = li % WSEG;
                const int k = k0 + row;
                const uint32_t sz = (k < 330) ? 16u : 0u;
                const int kk = (k < 330) ? k : 0;
                cp16z(sbase + OFF_W + row * PW + seg * 16, Wm + kk * OUT + seg * 8, sz);
            }
        }
        asm volatile("cp.async.commit_group;" ::: "memory");
    };

    issue(0);

    for (int c = 0; c < NCK; ++c) {
        if (c + 1 < NCK) {
            issue(c + 1);
            asm volatile("cp.async.wait_group 1;" ::: "memory");
        } else {
            asm volatile("cp.async.wait_group 0;" ::: "memory");
        }
        __syncthreads();

        const uint32_t sbase = sb0 + (c & 1) * STAGE;
        uint32_t bh[2][4], bl[2][4];
#pragma unroll
        for (int p = 0; p < 2; ++p) {
            const uint32_t boff = (uint32_t)((wn * 32 + p * 16) * 2);
            ldmx4t(bh[p], sbase + OFF_XH + b_lmT + boff);
            ldmx4t(bl[p], sbase + OFF_XL + b_lmT + boff);
        }
#pragma unroll
        for (int mi = 0; mi < 4; ++mi) {
            const uint32_t aoff = (uint32_t)((wm * 64 + mi * 16) * 2);
            uint32_t aw[4];
            ldmx4t(aw, sbase + OFF_W + a_lmT + aoff);
#pragma unroll
            for (int nj = 0; nj < 4; ++nj) {
                const int p = nj >> 1, h = (nj & 1) << 1;
                mmaf16(acc[mi][nj], aw, bh[p][h], bh[p][h + 1]);
                mmaf16(acc[mi][nj], aw, bl[p][h], bl[p][h + 1]);
            }
        }
        __syncthreads();
    }

    // stage Y^T[o][n] in smem (odd pitch PY; scalar stores)
    float* Ysm = (float*)sm;
    const int gid = lane >> 2;
    const int tig = lane & 3;
#pragma unroll
    for (int mi = 0; mi < 4; ++mi) {
#pragma unroll
        for (int nj = 0; nj < 4; ++nj) {
            const int o0 = wm * 64 + mi * 16 + gid;
            const int n = wn * 32 + nj * 8 + 2 * tig;
            Ysm[o0 * PY + n]           = acc[mi][nj][0];
            Ysm[o0 * PY + n + 1]       = acc[mi][nj][1];
            Ysm[(o0 + 8) * PY + n]     = acc[mi][nj][2];
            Ysm[(o0 + 8) * PY + n + 1] = acc[mi][nj][3];
        }
    }

    if (IS_P1) {
        float* Hsm = (float*)(sm + OUT * PY * 4);
        {
            const int o = tid & 63;
            const int ng = tid >> 6;
#pragma unroll
            for (int w = 0; w < NTILE / 4; ++w) {
                const int n = ng + w * 4;
                Hsm[n * 65 + o] = hx[(size_t)b * 65536 + (size_t)(n0 + n) * 64 + o];
            }
        }
        __syncthreads();
        {   // rh = sigmoid(Y + b0) * hx -> XT slot 5 (n-coalesced)
            const int n = tid & 127;
            const int og = tid >> 7;
#pragma unroll 1
            for (int ow = 0; ow < 32; ++ow) {
                const int o = og * 32 + ow;
                const float r = 1.f / (1.f + expf(-(Ysm[o * PY + n] + bias[o])));
                const float v = r * Hsm[n * 65 + o];
                __half h, l;
                split16(v, h, l);
                const size_t off = (size_t)((o + 2) * 64 + b) * 1024 + n0 + n;
                g_XTh[5][off] = h;
                g_XTl[5][off] = l;
            }
        }
        {   // u -> g_u (o-coalesced)
            const int o = tid & 63;
            const int ng = tid >> 6;
            const float b1 = bias[o + 64];
#pragma unroll 1
            for (int w = 0; w < NTILE / 4; ++w) {
                const int n = ng + w * 4;
                const float u = 1.f / (1.f + expf(-(Ysm[(o + 64) * PY + n] + b1)));
                g_u[(size_t)b * 65536 + (size_t)(n0 + n) * 64 + o] = u;
            }
        }
    } else {
        __syncthreads();
        const int o = tid & 63;
        const int nb = tid >> 6;
        const float b0 = bias[o];
#pragma unroll 1
        for (int it = 0; it < NTILE / 4; ++it) {
            const int n = nb + it * 4;
            const size_t idx = (size_t)b * 65536 + (size_t)(n0 + n) * 64 + o;
            const float cc = tanhf(Ysm[o * PY + n] + b0);
            const float u = g_u[idx], h = hx[idx];
            outp[idx] = u * h + (1.f - u) * cc;
        }
    }
}

// ============================================================================
// Host driver
// ============================================================================
extern "C" void kernel_launch(void* const* d_in, const int* in_sizes, int n_in,
                              void* d_out, int out_size) {
    const float* inp = (const float*)d_in[0];
    const float* hx  = (const float*)d_in[1];
    const float* S0  = (const float*)d_in[2];
    const float* S1  = (const float*)d_in[3];
    const float* Wo  = (const float*)d_in[4];
    const float* bo  = (const float*)d_in[5];
    const float* Wu  = (const float*)d_in[6];
    const float* bu  = (const float*)d_in[7];
    float* out = (float*)d_out;

    auto* p1 = proj_mma<128, 128, 272, 272, 129, true>;
    auto* p2 = proj_mma<64, 256, 528, 144, 257, false>;
    const int P1_SMEM = 128 * 129 * 4 + 128 * 65 * 4;   // 99328
    const int P2_SMEM = 64 * 257 * 4;                   // 65792

    cudaFuncSetAttribute(gemm_mma<false>, cudaFuncAttributeMaxDynamicSharedMemorySize, DSMEM_BYTES);
    cudaFuncSetAttribute(gemm_mma<true>,  cudaFuncAttributeMaxDynamicSharedMemorySize, DSMEM_BYTES);
    cudaFuncSetAttribute(p1, cudaFuncAttributeMaxDynamicSharedMemorySize, P1_SMEM);
    cudaFuncSetAttribute(p2, cudaFuncAttributeMaxDynamicSharedMemorySize, P2_SMEM);

    __half *gWo = nullptr, *gWu = nullptr;
    cudaGetSymbolAddress((void**)&gWo, g_Wo16);
    cudaGetSymbolAddress((void**)&gWu, g_Wu16);

    split_s_kernel<<<8192, 256>>>(S0, S1);
    split_w_kernel<<<248, 256>>>(Wo, Wu);
    build_inp_kernel<<<512, 256>>>(inp);
    build_h_kernel<<<dim3(16, 64), 256>>>(hx);

    const dim3 gG(NCOLS / NT, NNODES / MT, 2);   // (33, 8, 2)

    // pass 1 (X0 = slot 0)
    gemm_mma<false><<<gG, 256, DSMEM_BYTES>>>(0, 0, 1, 0);
    gemm_mma<true><<<gG, 256, DSMEM_BYTES>>>(1, 2, 2, 0);
    p1<<<dim3(8, 64), 256, P1_SMEM>>>(gWo, bo, hx, nullptr, 0);

    // pass 2 (X0 = slot 5, written by p1 + build_inp)
    gemm_mma<false><<<gG, 256, DSMEM_BYTES>>>(5, 0, 1, 5);
    gemm_mma<true><<<gG, 256, DSMEM_BYTES>>>(1, 2, 2, 5);
    p2<<<dim3(4, 64), 256, P2_SMEM>>>(gWu, bu, hx, out, 5);
}

// round 13
// speedup vs baseline: 5.0241x; 1.1446x over previous
#include <cuda_runtime.h>
#include <cuda_fp16.h>
#include <cstdint>
#include <math.h>

// ---------------- Problem constants ----------------
#define BDIM   64
#define NNODES 1024
#define UDIM   64
#define NCOLS  4224          // 66 features * 64 batch
#define NM     6             // slots: 0=X0(pass1), 1..4 diffusion, 5=X0(pass2)
#define XTSZ   (NCOLS * NNODES)

// Diffusion GEMM tiling (fp16: A single, B single)
#define MT 128
#define NT 128
#define KC 32
#define NCHUNK 32
#define ROWB 80
#define REG_BYTES (128 * ROWB)        // 10240
#define OFF_A  0
#define OFF_B  (1 * REG_BYTES)
#define STAGE_BYTES (2 * REG_BYTES)   // 20480
#define DSMEM_BYTES 68096             // max(2*20480, epilogue 128*133*4)

// ---------------- Device scratch ----------------
__device__ __align__(256) __half g_XT[NM][XTSZ];
__device__ __align__(256) __half g_S16[2][1024 * 1024];
__device__ __align__(256) __half g_Wo16[330 * 128];
__device__ __align__(256) __half g_Wu16[330 * 64];
__device__ __align__(256) float g_u[BDIM * NNODES * UDIM];

// ---------------- helpers ----------------
__device__ __forceinline__ uint32_t smem_u32(const void* p) {
    uint32_t a;
    asm("{ .reg .u64 t; cvta.to.shared.u64 t, %1; cvt.u32.u64 %0, t; }" : "=r"(a) : "l"(p));
    return a;
}
__device__ __forceinline__ void cp16(uint32_t saddr, const void* gaddr) {
    asm volatile("cp.async.cg.shared.global [%0], [%1], 16;" :: "r"(saddr), "l"(gaddr));
}
__device__ __forceinline__ void cp16z(uint32_t saddr, const void* gaddr, uint32_t srcsize) {
    asm volatile("cp.async.cg.shared.global [%0], [%1], 16, %2;"
                 :: "r"(saddr), "l"(gaddr), "r"(srcsize));
}
__device__ __forceinline__ void ldmx4a(uint32_t* r, uint32_t addr) {
    asm volatile("ldmatrix.sync.aligned.m8n8.x4.shared.b16 {%0,%1,%2,%3}, [%4];"
                 : "=r"(r[0]), "=r"(r[1]), "=r"(r[2]), "=r"(r[3]) : "r"(addr));
}
__device__ __forceinline__ void ldmx4t(uint32_t* r, uint32_t addr) {
    asm volatile("ldmatrix.sync.aligned.m8n8.x4.trans.shared.b16 {%0,%1,%2,%3}, [%4];"
                 : "=r"(r[0]), "=r"(r[1]), "=r"(r[2]), "=r"(r[3]) : "r"(addr));
}
__device__ __forceinline__ void mmaf16(float* c, const uint32_t* a, uint32_t b0, uint32_t b1) {
    asm volatile(
        "mma.sync.aligned.m16n8k16.row.col.f32.f16.f16.f32 "
        "{%0,%1,%2,%3}, {%4,%5,%6,%7}, {%8,%9}, {%0,%1,%2,%3};"
        : "+f"(c[0]), "+f"(c[1]), "+f"(c[2]), "+f"(c[3])
        : "r"(a[0]), "r"(a[1]), "r"(a[2]), "r"(a[3]), "r"(b0), "r"(b1));
}

// ============================================================================
// fused preprocessing: S -> fp16, W -> fp16, input rows -> slots 0 & 5
// ============================================================================
#define PRE_TOTAL (2097152 + 63360 + 131072)
__global__ void pre_kernel(const float* __restrict__ S0, const float* __restrict__ S1,
                           const float* __restrict__ Wo, const float* __restrict__ Wu,
                           const float* __restrict__ inp) {
    int idx = blockIdx.x * 256 + threadIdx.x;
    if (idx < 2097152) {
        int z = idx >> 20;
        int e = idx & 1048575;
        g_S16[z][e] = __float2half((z ? S1 : S0)[e]);
    } else if (idx < 2097152 + 63360) {
        int e = idx - 2097152;
        if (e < 42240) g_Wo16[e] = __float2half(Wo[e]);
        else           g_Wu16[e - 42240] = __float2half(Wu[e - 42240]);
    } else if (idx < PRE_TOTAL) {
        int e = idx - (2097152 + 63360);
        int c = e >> 10, i = e & 1023;
        int f = c >> 6, b = c & 63;
        __half h = __float2half(inp[b * 2048 + i * 2 + f]);
        g_XT[0][c * 1024 + i] = h;
        g_XT[5][c * 1024 + i] = h;
    }
}

// hidden rows from hx (pass 1) via smem transpose
__global__ __launch_bounds__(256)
void build_h_kernel(const float* __restrict__ hsrc) {
    __shared__ float T[64][65];
    const int i0 = blockIdx.x * 64;
    const int b  = blockIdx.y;
    const int tid = threadIdx.x;
    {
        const int u = tid & 63;
        const int iib = tid >> 6;
#pragma unroll
        for (int w = 0; w < 16; ++w) {
            const int ii = iib + w * 4;
            T[u][ii] = hsrc[(size_t)b * 65536 + (size_t)(i0 + ii) * 64 + u];
        }
    }
    __syncthreads();
    {
        const int ii = tid & 63;
        const int ub = tid >> 6;
#pragma unroll
        for (int w = 0; w < 16; ++w) {
            const int u = ub + w * 4;
            g_XT[0][(size_t)((u + 2) * 64 + b) * 1024 + i0 + ii] = __float2half(T[u][ii]);
        }
    }
}

// ============================================================================
// fp16 mma.sync diffusion GEMM: C = S[z] @ X[mi]  (CHEB: 2C - X0)
// grid (33, 8, 2), 256 threads. 32 MMA/warp/chunk.
// ============================================================================
template <bool CHEB>
__global__ __launch_bounds__(256)
void gemm_mma(int inBase, int inStride, int outBase, int x0Idx) {
    const int z = blockIdx.z;
    const int it = blockIdx.y, jt = blockIdx.x;
    const int mi_idx = inBase + z * inStride;
    const int mo = outBase + 2 * z;

    const __half* __restrict__ Am = g_S16[z];
    const __half* __restrict__ Bm = g_XT[mi_idx];
    __half* __restrict__ Cm = g_XT[mo];
    const __half* __restrict__ X0 = g_XT[x0Idx];

    extern __shared__ char sm[];
    const uint32_t sb0 = smem_u32(sm);

    const int tid = threadIdx.x;
    const int warp = tid >> 5;
    const int lane = tid & 31;
    const int wm = warp >> 2;
    const int wn = warp & 3;

    const size_t arow0 = (size_t)(it * MT) * 1024;
    const size_t brow0 = (size_t)(jt * NT) * 1024;

    const uint32_t a_lm = (uint32_t)((lane & 15) * ROWB + ((lane >> 4) << 4));
    const uint32_t b_lm = (uint32_t)((((lane >> 4) << 3) + (lane & 7)) * ROWB +
                                     (((lane >> 3) & 1) << 4));

    float acc[4][4][4];
#pragma unroll
    for (int i = 0; i < 4; i++)
#pragma unroll
        for (int j = 0; j < 4; j++)
#pragma unroll
            for (int r = 0; r < 4; r++) acc[i][j][r] = 0.f;

    auto issue = [&](int c) {
        const int buf = c & 1;
        const int k0 = c * KC;
        const uint32_t sbase = sb0 + buf * STAGE_BYTES;
#pragma unroll
        for (int q = 0; q < 4; q++) {
            int idx = tid + q * 256;
            int region = idx >> 9;             // 0..1
            int row = (idx >> 2) & 127;
            int seg = idx & 3;
            const __half* gp = region ? (Bm + brow0) : (Am + arow0);
            gp += (size_t)row * 1024 + k0 + seg * 8;
            cp16(sbase + region * REG_BYTES + row * ROWB + seg * 16, gp);
        }
        asm volatile("cp.async.commit_group;" ::: "memory");
    };

    issue(0);

    for (int c = 0; c < NCHUNK; ++c) {
        if (c + 1 < NCHUNK) {
            issue(c + 1);
            asm volatile("cp.async.wait_group 1;" ::: "memory");
        } else {
            asm volatile("cp.async.wait_group 0;" ::: "memory");
        }
        __syncthreads();

        const uint32_t sbase = sb0 + (c & 1) * STAGE_BYTES;
        const uint32_t aB = sbase + a_lm + (uint32_t)(wm * 64) * ROWB;
        const uint32_t bB = sbase + b_lm + (uint32_t)(wn * 32) * ROWB;

        // preload ALL B fragments (both k-steps)
        uint32_t bF[2][2][4];
#pragma unroll
        for (int s = 0; s < 2; ++s) {
            const uint32_t ks = (uint32_t)(s << 5);
#pragma unroll
            for (int p = 0; p < 2; ++p)
                ldmx4a(bF[s][p], bB + OFF_B + (uint32_t)(p * 16) * ROWB + ks);
        }
        // A ping-pong
        uint32_t aF[2][4];
        ldmx4a(aF[0], aB + OFF_A);
#pragma unroll
        for (int g = 0; g < 8; ++g) {
            const int s = g >> 2, mi = g & 3;
            const int cur = g & 1;
            if (g < 7) {
                const int g2 = g + 1;
                const uint32_t ao = (uint32_t)((g2 & 3) * 16) * ROWB +
                                    (uint32_t)((g2 >> 2) << 5);
                ldmx4a(aF[cur ^ 1], aB + OFF_A + ao);
            }
#pragma unroll
            for (int nj = 0; nj < 4; ++nj) {
                const int p = nj >> 1, h = (nj & 1) << 1;
                mmaf16(acc[mi][nj], aF[cur], bF[s][p][h], bF[s][p][h + 1]);
            }
        }
        __syncthreads();
    }

    // epilogue: stride-133 smem transpose; scalar stores (odd stride, 8B traps)
    float* Csm = (float*)sm;
    const int gid = lane >> 2;
    const int tig = lane & 3;
#pragma unroll
    for (int mi = 0; mi < 4; ++mi) {
#pragma unroll
        for (int nj = 0; nj < 4; ++nj) {
            const int r0 = wm * 64 + mi * 16 + gid;
            const int n = wn * 32 + nj * 8 + 2 * tig;
            Csm[r0 * 133 + n]           = acc[mi][nj][0];
            Csm[r0 * 133 + n + 1]       = acc[mi][nj][1];
            Csm[(r0 + 8) * 133 + n]     = acc[mi][nj][2];
            Csm[(r0 + 8) * 133 + n + 1] = acc[mi][nj][3];
        }
    }
    __syncthreads();

#pragma unroll 1
    for (int iter = 0; iter < 16; ++iter) {
        const int j = iter * 8 + warp;
        const size_t jg = (size_t)(jt * NT + j);
#pragma unroll
        for (int q = 0; q < 4; ++q) {
            const int i = lane + q * 32;
            const size_t ig = (size_t)(it * MT) + i;
            float y = Csm[i * 133 + j];
            if (CHEB)
                y = 2.f * y - __half2float(X0[jg * 1024 + ig]);
            Cm[jg * 1024 + ig] = __float2half(y);
        }
    }
}

// ============================================================================
// Tensor-core projection (fp16 single-term). K=330 padded to 336.
// IS_P1: r -> XT slot 5 hidden rows fused, u -> g_u.
// else : c = tanh(.), out = u*hx + (1-u)*c.
// ============================================================================
template <int OUT, int NTILE, int PX, int PW, int PY, bool IS_P1>
__global__ __launch_bounds__(256)
void proj_mma(const __half* __restrict__ Wm, const float* __restrict__ bias,
              const float* __restrict__ hx, float* __restrict__ outp, int x0slot) {
    constexpr int XSEG = NTILE / 8;
    constexpr int WSEG = OUT / 8;
    constexpr int OFF_X = 0;
    constexpr int OFF_W = 16 * PX;
    constexpr int STAGE = 16 * PX + 16 * PW;
    constexpr int TOTAL = 2 * NTILE + 2 * OUT;
    constexpr int NQ = (TOTAL + 255) / 256;
    constexpr int NCK = 21;
    constexpr int WN_CNT = NTILE / 32;

    const int n0 = blockIdx.x * NTILE;
    const int b  = blockIdx.y;

    extern __shared__ char sm[];
    const uint32_t sb0 = smem_u32(sm);

    const int tid = threadIdx.x;
    const int warp = tid >> 5;
    const int lane = tid & 31;
    const int wm = warp / WN_CNT;
    const int wn = warp % WN_CNT;

    const uint32_t a_lmT = (uint32_t)(((lane & 7) + ((lane >> 4) & 1) * 8) * PW +
                                      (((lane >> 3) & 1) << 4));
    const uint32_t b_lmT = (uint32_t)(((lane & 7) + ((lane >> 3) & 1) * 8) * PX +
                                      ((lane >> 4) << 4));

    float acc[4][4][4];
#pragma unroll
    for (int i = 0; i < 4; i++)
#pragma unroll
        for (int j = 0; j < 4; j++)
#pragma unroll
            for (int r = 0; r < 4; r++) acc[i][j][r] = 0.f;

    const __half* X0 = &g_XT[0][0];

    auto issue = [&](int c) {
        const uint32_t sbase = sb0 + (c & 1) * STAGE;
        const int k0 = c * 16;
#pragma unroll
        for (int q = 0; q < NQ; q++) {
            int idx = tid + q * 256;
            if (idx >= TOTAL) break;
            if (idx < 2 * NTILE) {
                const int row = idx / XSEG, seg = idx % XSEG;
                const int k = k0 + row;
                const uint32_t sz = (k < 330) ? 16u : 0u;
                const int kk = (k < 330) ? k : 0;
                const int f = kk / 5, m = kk - f * 5;
                const int mslot = (m == 0) ? x0slot : m;
                const __half* src = X0 + (size_t)mslot * XTSZ +
                                    (size_t)(f * 64 + b) * 1024 + n0 + seg * 8;
                cp16z(sbase + OFF_X + row * PX + seg * 16, src, sz);
            } else {
                const int li = idx - 2 * NTILE;
                const int row = li / WSEG, seg = li % WSEG;
                const int k = k0 + row;
                const uint32_t sz = (k < 330) ? 16u : 0u;
                const int kk = (k < 330) ? k : 0;
                cp16z(sbase + OFF_W + row * PW + seg * 16, Wm + kk * OUT + seg * 8, sz);
            }
        }
        asm volatile("cp.async.commit_group;" ::: "memory");
    };

    issue(0);

    for (int c = 0; c < NCK; ++c) {
        if (c + 1 < NCK) {
            issue(c + 1);
            asm volatile("cp.async.wait_group 1;" ::: "memory");
        } else {
            asm volatile("cp.async.wait_group 0;" ::: "memory");
        }
        __syncthreads();

        const uint32_t sbase = sb0 + (c & 1) * STAGE;
        uint32_t bF[2][4];
#pragma unroll
        for (int p = 0; p < 2; ++p)
            ldmx4t(bF[p], sbase + OFF_X + b_lmT + (uint32_t)((wn * 32 + p * 16) * 2));
#pragma unroll
        for (int mi = 0; mi < 4; ++mi) {
            uint32_t aw[4];
            ldmx4t(aw, sbase + OFF_W + a_lmT + (uint32_t)((wm * 64 + mi * 16) * 2));
#pragma unroll
            for (int nj = 0; nj < 4; ++nj) {
                const int p = nj >> 1, h = (nj & 1) << 1;
                mmaf16(acc[mi][nj], aw, bF[p][h], bF[p][h + 1]);
            }
        }
        __syncthreads();
    }

    // stage Y^T[o][n] in smem (odd pitch PY; scalar stores)
    float* Ysm = (float*)sm;
    const int gid = lane >> 2;
    const int tig = lane & 3;
#pragma unroll
    for (int mi = 0; mi < 4; ++mi) {
#pragma unroll
        for (int nj = 0; nj < 4; ++nj) {
            const int o0 = wm * 64 + mi * 16 + gid;
            const int n = wn * 32 + nj * 8 + 2 * tig;
            Ysm[o0 * PY + n]           = acc[mi][nj][0];
            Ysm[o0 * PY + n + 1]       = acc[mi][nj][1];
            Ysm[(o0 + 8) * PY + n]     = acc[mi][nj][2];
            Ysm[(o0 + 8) * PY + n + 1] = acc[mi][nj][3];
        }
    }

    if (IS_P1) {
        float* Hsm = (float*)(sm + OUT * PY * 4);
        {
            const int o = tid & 63;
            const int ng = tid >> 6;
#pragma unroll
            for (int w = 0; w < NTILE / 4; ++w) {
                const int n = ng + w * 4;
                Hsm[n * 65 + o] = hx[(size_t)b * 65536 + (size_t)(n0 + n) * 64 + o];
            }
        }
        __syncthreads();
        {   // rh = sigmoid(Y + b0) * hx -> XT slot 5 (n-coalesced)
            const int n = tid & 127;
            const int og = tid >> 7;
#pragma unroll 1
            for (int ow = 0; ow < 32; ++ow) {
                const int o = og * 32 + ow;
                const float r = 1.f / (1.f + expf(-(Ysm[o * PY + n] + bias[o])));
                const float v = r * Hsm[n * 65 + o];
                g_XT[5][(size_t)((o + 2) * 64 + b) * 1024 + n0 + n] = __float2half(v);
            }
        }
        {   // u -> g_u (o-coalesced)
            const int o = tid & 63;
            const int ng = tid >> 6;
            const float b1 = bias[o + 64];
#pragma unroll 1
            for (int w = 0; w < NTILE / 4; ++w) {
                const int n = ng + w * 4;
                const float u = 1.f / (1.f + expf(-(Ysm[(o + 64) * PY + n] + b1)));
                g_u[(size_t)b * 65536 + (size_t)(n0 + n) * 64 + o] = u;
            }
        }
    } else {
        __syncthreads();
        const int o = tid & 63;
        const int nb = tid >> 6;
        const float b0 = bias[o];
#pragma unroll 1
        for (int it = 0; it < NTILE / 4; ++it) {
            const int n = nb + it * 4;
            const size_t idx = (size_t)b * 65536 + (size_t)(n0 + n) * 64 + o;
            const float cc = tanhf(Ysm[o * PY + n] + b0);
            const float u = g_u[idx], h = hx[idx];
            outp[idx] = u * h + (1.f - u) * cc;
        }
    }
}

// ============================================================================
// Host driver
// ============================================================================
extern "C" void kernel_launch(void* const* d_in, const int* in_sizes, int n_in,
                              void* d_out, int out_size) {
    const float* inp = (const float*)d_in[0];
    const float* hx  = (const float*)d_in[1];
    const float* S0  = (const float*)d_in[2];
    const float* S1  = (const float*)d_in[3];
    const float* Wo  = (const float*)d_in[4];
    const float* bo  = (const float*)d_in[5];
    const float* Wu  = (const float*)d_in[6];
    const float* bu  = (const float*)d_in[7];
    float* out = (float*)d_out;

    auto* p1 = proj_mma<128, 128, 272, 272, 129, true>;
    auto* p2 = proj_mma<64, 256, 528, 144, 257, false>;
    const int P1_SMEM = 128 * 129 * 4 + 128 * 65 * 4;   // 99328 (> 2*8704)
    const int P2_SMEM = 64 * 257 * 4;                   // 65792 (> 2*10752)

    cudaFuncSetAttribute(gemm_mma<false>, cudaFuncAttributeMaxDynamicSharedMemorySize, DSMEM_BYTES);
    cudaFuncSetAttribute(gemm_mma<true>,  cudaFuncAttributeMaxDynamicSharedMemorySize, DSMEM_BYTES);
    cudaFuncSetAttribute(p1, cudaFuncAttributeMaxDynamicSharedMemorySize, P1_SMEM);
    cudaFuncSetAttribute(p2, cudaFuncAttributeMaxDynamicSharedMemorySize, P2_SMEM);

    __half *gWo = nullptr, *gWu = nullptr;
    cudaGetSymbolAddress((void**)&gWo, g_Wo16);
    cudaGetSymbolAddress((void**)&gWu, g_Wu16);

    pre_kernel<<<(PRE_TOTAL + 255) / 256, 256>>>(S0, S1, Wo, Wu, inp);
    build_h_kernel<<<dim3(16, 64), 256>>>(hx);

    const dim3 gG(NCOLS / NT, NNODES / MT, 2);   // (33, 8, 2)

    // pass 1 (X0 = slot 0)
    gemm_mma<false><<<gG, 256, DSMEM_BYTES>>>(0, 0, 1, 0);
    gemm_mma<true><<<gG, 256, DSMEM_BYTES>>>(1, 2, 2, 0);
    p1<<<dim3(8, 64), 256, P1_SMEM>>>(gWo, bo, hx, nullptr, 0);

    // pass 2 (X0 = slot 5, written by p1 + pre_kernel)
    gemm_mma<false><<<gG, 256, DSMEM_BYTES>>>(5, 0, 1, 5);
    gemm_mma<true><<<gG, 256, DSMEM_BYTES>>>(1, 2, 2, 5);
    p2<<<dim3(4, 64), 256, P2_SMEM>>>(gWu, bu, hx, out, 5);
}